// round 11
// baseline (speedup 1.0000x reference)
#include <cuda_runtime.h>
#include <cuda_bf16.h>
#include <math.h>
#include <stdint.h>

// ---------------- problem constants ----------------
#define NQ 1024
#define ND 200000
#define NF 64
#define NK 32
#define NC 16
#define NH 128

#define MT 128           // queries per CTA
#define NT 128           // points per smem stage
#define NSL 55           // main-pass slices -> grid (8,55)=440 CTAs = one occ-3 wave
#define MAIN_TILES 29    // 55*29*128 = 204160 >= 200000
#define NDPAD 204160
#define SN 8192          // sample size
#define SAMPLE_SLICES 32
#define SAMPLE_TILES 2   // 32*2*128 = 8192
#define CAP 4096
#define MARGIN 4.0f      // mma approx + bf16-store safety margin
#define BIGV 3.0e38f

// ---------------- static device scratch ----------------
__device__ float          g_xxp[NDPAD];
__device__ __nv_bfloat16  g_Xb[(size_t)NDPAD * NF];
__device__ __nv_bfloat16  g_Qb[(size_t)NQ * NF];
__device__ unsigned short g_Du[(size_t)NQ * SN];   // bf16 sample scores
__device__ float          g_tau[NQ];
__device__ int            g_cnt[NQ];
__device__ int            g_si[(size_t)NQ * CAP];
__device__ int            g_topk[NQ * NK];

// ---------------- helpers ----------------
__device__ __forceinline__ uint32_t smem_u32(const void* p) {
    uint32_t a;
    asm("{ .reg .u64 t; cvta.to.shared.u64 t, %1; cvt.u32.u64 %0, t; }" : "=r"(a) : "l"(p));
    return a;
}
#define SWZ128(o) ((o) ^ (((o) >> 3) & 0x70))

__device__ __forceinline__ void cpa16(uint32_t d, const void* s) {
    asm volatile("cp.async.cg.shared.global [%0], [%1], 16;" :: "r"(d), "l"(s) : "memory");
}
#define CPA_COMMIT() asm volatile("cp.async.commit_group;" ::: "memory")
#define CPA_WAIT1()  asm volatile("cp.async.wait_group 1;" ::: "memory")

__device__ __forceinline__ void ldsm4(uint32_t* r, uint32_t a) {
    asm volatile("ldmatrix.sync.aligned.m8n8.x4.shared.b16 {%0,%1,%2,%3}, [%4];"
                 : "=r"(r[0]), "=r"(r[1]), "=r"(r[2]), "=r"(r[3]) : "r"(a));
}
__device__ __forceinline__ void mma16816(float* d, const uint32_t* a, const uint32_t* b) {
    asm volatile(
        "mma.sync.aligned.m16n8k16.row.col.f32.bf16.bf16.f32 "
        "{%0,%1,%2,%3}, {%4,%5,%6,%7}, {%8,%9}, {%0,%1,%2,%3};"
        : "+f"(d[0]), "+f"(d[1]), "+f"(d[2]), "+f"(d[3])
        : "r"(a[0]), "r"(a[1]), "r"(a[2]), "r"(a[3]), "r"(b[0]), "r"(b[1]));
}
__device__ __forceinline__ unsigned short f2bf(float v) {
    __nv_bfloat16 h = __float2bfloat16(v);
    return *(unsigned short*)&h;
}

// ---------------- smem layout (bytes) ----------------
// Q: 16KB, X stages: 3 x 16KB, norms: 3 x 512B, tau: 512B
#define SMQ     0
#define SMX(s)  (16384 + (s) * 16384)
#define SMXX(s) (65536 + (s) * 512)
#define SMTAU   67072
#define SM_TOTAL 67584

// ============================================================
// prep_x: exact fp32 norms + bf16 conversion + padding
// ============================================================
__global__ void prep_x_kernel(const float* __restrict__ Xd) {
    int r = blockIdx.x * 64 + (threadIdx.x >> 2);
    int part = threadIdx.x & 3;
    if (r >= NDPAD) return;
    uint4* dst = (uint4*)(g_Xb + (size_t)r * NF) + part * 2;
    if (r < ND) {
        const float4* row = (const float4*)(Xd + (size_t)r * NF) + part * 4;
        float4 v[4];
        float s = 0.f;
#pragma unroll
        for (int l = 0; l < 4; l++) {
            v[l] = row[l];
            s += v[l].x * v[l].x + v[l].y * v[l].y + v[l].z * v[l].z + v[l].w * v[l].w;
        }
        s += __shfl_xor_sync(0xffffffffu, s, 1);
        s += __shfl_xor_sync(0xffffffffu, s, 2);
        if (part == 0) g_xxp[r] = s;
        unsigned u[8];
#pragma unroll
        for (int l = 0; l < 4; l++) {
            __nv_bfloat162 h0 = __floats2bfloat162_rn(v[l].x, v[l].y);
            __nv_bfloat162 h1 = __floats2bfloat162_rn(v[l].z, v[l].w);
            u[l * 2]     = *(unsigned*)&h0;
            u[l * 2 + 1] = *(unsigned*)&h1;
        }
        dst[0] = make_uint4(u[0], u[1], u[2], u[3]);
        dst[1] = make_uint4(u[4], u[5], u[6], u[7]);
    } else {
        if (part == 0) g_xxp[r] = BIGV;
        uint4 z = make_uint4(0, 0, 0, 0);
        dst[0] = z; dst[1] = z;
    }
}

// prep_q: g_Qb = bf16(-2 * x); also zeroes g_cnt (fused)
__global__ void prep_q_kernel(const float* __restrict__ xq) {
    int i = blockIdx.x * 256 + threadIdx.x;
    float2 v = ((const float2*)xq)[i];
    __nv_bfloat162 h = __floats2bfloat162_rn(-2.f * v.x, -2.f * v.y);
    ((__nv_bfloat162*)g_Qb)[i] = h;
    if (i < NQ) g_cnt[i] = 0;
}

// ============================================================
// MMA kernel: warp tile 32q x 32n (4x2 warp grid), CTA 128q x 128n/stage,
// 3-stage cp.async ring, one __syncthreads per stage, occ 3.
// A (Q) fragments hoisted for the whole slice (32 regs).
// MODE 0: write bf16 approx scores of sample region to g_Du
// MODE 1: filter vs g_tau (min-tree fast path), append survivors
// ============================================================
template <int MODE, int NTILES>
__global__ void __launch_bounds__(256, 3)
mma_kernel() {
    extern __shared__ char smem[];
    const uint32_t sb = smem_u32(smem);
    const int tid = threadIdx.x;
    const int lane = tid & 31;
    const int wid = tid >> 5;
    const int mtile = blockIdx.x;
    const int base = blockIdx.y * NTILES * NT;

    // load Q tile into swizzled smem (128 rows x 128B)
    {
        const uint4* qsrc = (const uint4*)(g_Qb + (size_t)mtile * MT * NF);
#pragma unroll
        for (int c = 0; c < 4; c++) {
            int ch = tid + c * 256;
            int row = ch >> 3, col = ch & 7;
            *(uint4*)(smem + SMQ + SWZ128(row * 128 + col * 16)) = qsrc[ch];
        }
    }
    if (MODE == 1 && tid < MT) ((float*)(smem + SMTAU))[tid] = g_tau[mtile * MT + tid];

    // prologue: issue stages 0 and 1
#pragma unroll
    for (int s = 0; s < 2; s++) {
        if (s < NTILES) {
            const uint4* xs = (const uint4*)(g_Xb + (size_t)(base + s * NT) * NF);
#pragma unroll
            for (int c = 0; c < 4; c++) {
                int ch = tid + c * 256;
                int row = ch >> 3, col = ch & 7;
                cpa16(sb + SMX(s) + SWZ128(row * 128 + col * 16), xs + ch);
            }
            if (tid < 32) cpa16(sb + SMXX(s) + tid * 16, g_xxp + base + s * NT + tid * 4);
        }
        CPA_COMMIT();
    }
    __syncthreads();   // Q (and tau) visible

    const int wr = wid >> 1;          // 0..3 : q-row block of 32
    const int wc = wid & 1;           // 0..1 : n-col block of 32 (within a 64 half)
    const int m0 = wr * 32;
    const int nb = wc * 32;
    const int tq = lane >> 2;         // row within 8
    const int tn2 = (lane & 3) * 2;   // col pair within 8

    // ldmatrix lane addressing
    const int a_row = lane & 15, a_kh = lane >> 4;
    const int b_row = (lane & 7) | ((lane >> 4) << 3), b_kh = (lane >> 3) & 1;

    // hoist A (Q) fragments: [ks][mf*4 + i]  (32 regs)
    uint32_t afr[4][8];
#pragma unroll
    for (int ks = 0; ks < 4; ks++)
#pragma unroll
        for (int mf = 0; mf < 2; mf++) {
            uint32_t addr = sb + SMQ +
                SWZ128((m0 + mf * 16 + a_row) * 128 + ks * 32 + a_kh * 16);
            ldsm4(&afr[ks][mf * 4], addr);
        }

    // per-thread taus (rows: mf in {0,1}, h in {0,1}) + tmax for fast path
    float tr[4], tmax = -BIGV;
    if (MODE == 1) {
        const float* tsm = (const float*)(smem + SMTAU);
#pragma unroll
        for (int mf = 0; mf < 2; mf++)
#pragma unroll
            for (int h = 0; h < 2; h++) {
                tr[mf * 2 + h] = tsm[m0 + mf * 16 + h * 8 + tq];
                tmax = fmaxf(tmax, tr[mf * 2 + h]);
            }
    }

    for (int t = 0; t < NTILES; t++) {
        const int t0 = base + t * NT;
        const int st = t % 3;
        const uint32_t xb  = SMX(st);
        const uint32_t xxb = SMXX(st);

        CPA_WAIT1();          // stage t complete (only stage t+1 may be pending)
        __syncthreads();      // all warps done with stage (t+2)%3's previous life

        // issue prefetch of stage t+2 (after the barrier -> no overwrite hazard)
        if (t + 2 < NTILES) {
            const int ps = (t + 2) % 3;
            const uint4* xs = (const uint4*)(g_Xb + (size_t)(t0 + 2 * NT) * NF);
#pragma unroll
            for (int c = 0; c < 4; c++) {
                int ch = tid + c * 256;
                int row = ch >> 3, col = ch & 7;
                cpa16(sb + SMX(ps) + SWZ128(row * 128 + col * 16), xs + ch);
            }
            if (tid < 32) cpa16(sb + SMXX(ps) + tid * 16, g_xxp + t0 + 2 * NT + tid * 4);
        }
        CPA_COMMIT();         // always commit to keep group count uniform

        // compute the 128-point stage as two 64-col halves
#pragma unroll
        for (int half = 0; half < 2; half++) {
            const int nh = half * 64 + nb;     // n-offset within stage (0..127)

            float d[2][4][4];
#pragma unroll
            for (int i = 0; i < 2; i++)
#pragma unroll
                for (int j = 0; j < 4; j++)
#pragma unroll
                    for (int k = 0; k < 4; k++) d[i][j][k] = 0.f;

#pragma unroll
            for (int ks = 0; ks < 4; ks++) {
                uint32_t b[4][2];
#pragma unroll
                for (int h = 0; h < 2; h++) {
                    uint32_t r[4];
                    uint32_t addr = sb + xb +
                        SWZ128((nh + h * 16 + b_row) * 128 + ks * 32 + b_kh * 16);
                    ldsm4(r, addr);
                    b[h * 2][0] = r[0]; b[h * 2][1] = r[1];
                    b[h * 2 + 1][0] = r[2]; b[h * 2 + 1][1] = r[3];
                }
#pragma unroll
                for (int mf = 0; mf < 2; mf++)
#pragma unroll
                    for (int nf = 0; nf < 4; nf++)
                        mma16816(d[mf][nf], &afr[ks][mf * 4], b[nf]);
            }

            // epilogue for this half: add ||X||^2, then fast-path filter
            const float* xxs = (const float*)(smem + xxb);
            float2 xv[4];
#pragma unroll
            for (int nf = 0; nf < 4; nf++) xv[nf] = *(const float2*)(xxs + nh + nf * 8 + tn2);

            float vmin = BIGV;
#pragma unroll
            for (int mf = 0; mf < 2; mf++)
#pragma unroll
                for (int nf = 0; nf < 4; nf++) {
                    d[mf][nf][0] += xv[nf].x;
                    d[mf][nf][1] += xv[nf].y;
                    d[mf][nf][2] += xv[nf].x;
                    d[mf][nf][3] += xv[nf].y;
                    if (MODE == 1)
                        vmin = fminf(vmin, fminf(fminf(d[mf][nf][0], d[mf][nf][1]),
                                                 fminf(d[mf][nf][2], d[mf][nf][3])));
                }

            if (MODE == 0) {
#pragma unroll
                for (int mf = 0; mf < 2; mf++)
#pragma unroll
                    for (int h = 0; h < 2; h++) {
                        const int gq = mtile * MT + m0 + mf * 16 + h * 8 + tq;
                        unsigned short* dst = g_Du + (size_t)gq * SN + (t0 + nh + tn2);
#pragma unroll
                        for (int nf = 0; nf < 4; nf++) {
                            unsigned short u0 = f2bf(d[mf][nf][h * 2]);
                            unsigned short u1 = f2bf(d[mf][nf][h * 2 + 1]);
                            *(unsigned*)(dst + nf * 8) = (unsigned)u0 | ((unsigned)u1 << 16);
                        }
                    }
            } else if (vmin <= tmax) {   // rare slow path (~1e-3 of thread-tiles)
#pragma unroll
                for (int mf = 0; mf < 2; mf++)
#pragma unroll
                    for (int h = 0; h < 2; h++) {
                        const int gq = mtile * MT + m0 + mf * 16 + h * 8 + tq;
                        const float tau = tr[mf * 2 + h];
#pragma unroll
                        for (int nf = 0; nf < 4; nf++) {
                            float v0 = d[mf][nf][h * 2];
                            float v1 = d[mf][nf][h * 2 + 1];
                            if (v0 <= tau) {
                                int pos = atomicAdd(&g_cnt[gq], 1);
                                if (pos < CAP) g_si[(size_t)gq * CAP + pos] = t0 + nh + nf * 8 + tn2;
                            }
                            if (v1 <= tau) {
                                int pos = atomicAdd(&g_cnt[gq], 1);
                                if (pos < CAP) g_si[(size_t)gq * CAP + pos] = t0 + nh + nf * 8 + tn2 + 1;
                            }
                        }
                    }
            }
        }
    }
}

// ============================================================
// tau: radix-select 32nd smallest bf16 sample score + margin
// 8 warp-private histograms to kill smem-atomic serialization.
// ============================================================
__global__ void tau_kernel() {
    __shared__ unsigned short sU[SN];        // 16KB
    __shared__ unsigned hist[8][256];        // 8KB
    __shared__ unsigned s_prefix;
    __shared__ int s_rank;
    const int b = blockIdx.x, tid = threadIdx.x;
    const int w = tid >> 5;

    for (int i = tid; i < SN / 2; i += 256) {
        unsigned v = ((const unsigned*)(g_Du + (size_t)b * SN))[i];
        unsigned short u0 = (unsigned short)v, u1 = (unsigned short)(v >> 16);
        u0 = (u0 & 0x8000u) ? (unsigned short)~u0 : (unsigned short)(u0 | 0x8000u);
        u1 = (u1 & 0x8000u) ? (unsigned short)~u1 : (unsigned short)(u1 | 0x8000u);
        ((unsigned*)sU)[i] = (unsigned)u0 | ((unsigned)u1 << 16);
    }
    if (tid == 0) { s_prefix = 0u; s_rank = NK; }
    __syncthreads();

#pragma unroll
    for (int lev = 0; lev < 2; lev++) {
        const int sh = 8 - 8 * lev;
#pragma unroll
        for (int j = 0; j < 8; j++) hist[j][tid] = 0;
        __syncthreads();
        const unsigned pfx = s_prefix;
        for (int i = tid; i < SN; i += 256) {
            unsigned u = sU[i];
            if (lev == 0 || (u & 0xFF00u) == pfx)
                atomicAdd(&hist[w][(u >> sh) & 255u], 1u);
        }
        __syncthreads();
        // reduce 8 warp hists into hist[0]
        unsigned tot = hist[0][tid];
#pragma unroll
        for (int j = 1; j < 8; j++) tot += hist[j][tid];
        hist[0][tid] = tot;
        __syncthreads();
        if (tid == 0) {
            int r = s_rank;
            unsigned cum = 0;
            for (int k = 0; k < 256; k++) {
                unsigned h = hist[0][k];
                if (cum + h >= (unsigned)r) {
                    s_rank = r - (int)cum;
                    s_prefix = pfx | ((unsigned)k << sh);
                    break;
                }
                cum += h;
            }
        }
        __syncthreads();
    }
    if (tid == 0) {
        unsigned short u = (unsigned short)s_prefix;
        unsigned short bb = (u & 0x8000u) ? (unsigned short)(u ^ 0x8000u) : (unsigned short)~u;
        g_tau[b] = __uint_as_float((unsigned)bb << 16) + MARGIN;
    }
}

// ============================================================
// rescore + select fused: exact fp32 scores into smem, then
// exact top-32 with (val, idx) tie-break. One block per query.
// ============================================================
__global__ void rsel_kernel(const float* __restrict__ xq, const float* __restrict__ Xd) {
    __shared__ float sv[CAP];
    __shared__ int si[CAP];
    __shared__ float xs[NF];
    __shared__ float rv[8];
    __shared__ int ri[8], rp[8];
    const int b = blockIdx.x, tid = threadIdx.x;
    const int w = tid >> 5, lane = tid & 31;

    if (tid < NF) xs[tid] = xq[(size_t)b * NF + tid];
    int c = g_cnt[b]; if (c > CAP) c = CAP;
    const int cpad = (c + 255) & ~255;
    for (int i = tid; i < cpad; i += 256) { sv[i] = BIGV; si[i] = 0x7FFFFFFF; }
    __syncthreads();

    // exact rescore (warp per survivor)
    float2 xv = *(const float2*)(xs + 2 * lane);
    for (int s = w; s < c; s += 8) {
        int n = g_si[(size_t)b * CAP + s];
        float2 Xv = *(const float2*)(Xd + (size_t)n * NF + 2 * lane);
        float p = xv.x * Xv.x + xv.y * Xv.y;
#pragma unroll
        for (int off = 16; off > 0; off >>= 1) p += __shfl_xor_sync(0xffffffffu, p, off);
        if (lane == 0) { sv[s] = g_xxp[n] - 2.f * p; si[s] = n; }
    }
    __syncthreads();

    // exact top-32 selection
    for (int r = 0; r < NK; r++) {
        float bv = BIGV; int bi = 0x7FFFFFFF; int bp = 0;
        for (int i = tid; i < cpad; i += 256) {
            float v = sv[i]; int ix = si[i];
            if (v < bv || (v == bv && ix < bi)) { bv = v; bi = ix; bp = i; }
        }
#pragma unroll
        for (int off = 16; off > 0; off >>= 1) {
            float ov = __shfl_down_sync(0xffffffffu, bv, off);
            int oi = __shfl_down_sync(0xffffffffu, bi, off);
            int op = __shfl_down_sync(0xffffffffu, bp, off);
            if (ov < bv || (ov == bv && oi < bi)) { bv = ov; bi = oi; bp = op; }
        }
        if (lane == 0) { rv[w] = bv; ri[w] = bi; rp[w] = bp; }
        __syncthreads();
        if (tid == 0) {
            for (int wi = 1; wi < 8; wi++)
                if (rv[wi] < rv[0] || (rv[wi] == rv[0] && ri[wi] < ri[0])) {
                    rv[0] = rv[wi]; ri[0] = ri[wi]; rp[0] = rp[wi];
                }
            g_topk[b * NK + r] = ri[0];
            sv[rp[0]] = BIGV; si[rp[0]] = 0x7FFFFFFF;
        }
        __syncthreads();
    }
}

// ============================================================
// mlp: gather neighbors + gated MLP head (one block per query)
// ============================================================
__global__ void mlp_kernel(const float* __restrict__ xq, const float* __restrict__ Xd,
                           const float* __restrict__ yv, const float* __restrict__ Wg,
                           const float* __restrict__ bg, const float* __restrict__ W1,
                           const float* __restrict__ b1, const float* __restrict__ Wl,
                           const float* __restrict__ bl, float* __restrict__ out) {
    __shared__ float nfs[NK * 65];
    __shared__ float Wgs[65 * NC];
    __shared__ float gs[NK * NC];
    __shared__ float xa[NF + NC];
    __shared__ float red[4];
    __shared__ int idx[NK];
    const int b = blockIdx.x, tid = threadIdx.x;

    if (tid < NK) idx[tid] = g_topk[b * NK + tid];
    for (int i = tid; i < 65 * NC; i += 128) Wgs[i] = Wg[i];
    __syncthreads();
    for (int i = tid; i < NK * NF; i += 128) {
        int k = i >> 6, f = i & 63;
        nfs[k * 65 + f] = Xd[(size_t)idx[k] * NF + f];
    }
    if (tid < NK) nfs[tid * 65 + 64] = yv[idx[tid]];
    __syncthreads();

    {
        int k = tid & 31, c0 = (tid >> 5) * 4;
        float a0 = bg[c0], a1 = bg[c0 + 1], a2 = bg[c0 + 2], a3 = bg[c0 + 3];
#pragma unroll 5
        for (int j = 0; j < 65; j++) {
            float v = nfs[k * 65 + j];
            a0 += v * Wgs[j * NC + c0];
            a1 += v * Wgs[j * NC + c0 + 1];
            a2 += v * Wgs[j * NC + c0 + 2];
            a3 += v * Wgs[j * NC + c0 + 3];
        }
        gs[k * NC + c0] = tanhf(a0);
        gs[k * NC + c0 + 1] = tanhf(a1);
        gs[k * NC + c0 + 2] = tanhf(a2);
        gs[k * NC + c0 + 3] = tanhf(a3);
    }
    __syncthreads();
    if (tid < NF) {
        xa[tid] = xq[(size_t)b * NF + tid];
    } else if (tid < NF + NC) {
        int c = tid - NF;
        float s = 0.f;
#pragma unroll
        for (int k = 0; k < NK; k++) s += gs[k * NC + c];
        xa[tid] = s;
    }
    __syncthreads();

    float s = b1[tid];
#pragma unroll 8
    for (int i = 0; i < NF + NC; i++) s += xa[i] * W1[i * NH + tid];
    float oh = tanhf(s);
    float r = oh * Wl[tid];
#pragma unroll
    for (int off = 16; off > 0; off >>= 1) r += __shfl_down_sync(0xffffffffu, r, off);
    if ((tid & 31) == 0) red[tid >> 5] = r;
    __syncthreads();
    if (tid == 0) {
        float t = red[0] + red[1] + red[2] + red[3] + bl[0];
        out[b] = 1.f / (1.f + expf(-t));
    }
}

// ============================================================
extern "C" void kernel_launch(void* const* d_in, const int* in_sizes, int n_in,
                              void* d_out, int out_size) {
    (void)in_sizes; (void)n_in; (void)out_size;
    const float* xq = (const float*)d_in[0];
    const float* Xd = (const float*)d_in[1];
    const float* yv = (const float*)d_in[2];
    const float* Wg = (const float*)d_in[3];
    const float* bg = (const float*)d_in[4];
    const float* W1 = (const float*)d_in[5];
    const float* b1 = (const float*)d_in[6];
    const float* Wl = (const float*)d_in[7];
    const float* bl = (const float*)d_in[8];
    float* out = (float*)d_out;

    cudaFuncSetAttribute(mma_kernel<0, SAMPLE_TILES>, cudaFuncAttributeMaxDynamicSharedMemorySize, SM_TOTAL);
    cudaFuncSetAttribute(mma_kernel<1, MAIN_TILES>, cudaFuncAttributeMaxDynamicSharedMemorySize, SM_TOTAL);

    prep_x_kernel<<<NDPAD / 64, 256>>>(Xd);
    prep_q_kernel<<<128, 256>>>(xq);
    mma_kernel<0, SAMPLE_TILES><<<dim3(NQ / MT, SAMPLE_SLICES), 256, SM_TOTAL>>>();
    tau_kernel<<<NQ, 256>>>();
    mma_kernel<1, MAIN_TILES><<<dim3(NQ / MT, NSL), 256, SM_TOTAL>>>();
    rsel_kernel<<<NQ, 256>>>(xq, Xd);
    mlp_kernel<<<NQ, 128>>>(xq, Xd, yv, Wg, bg, W1, b1, Wl, bl, out);
}

// round 12
// speedup vs baseline: 1.2995x; 1.2995x over previous
#include <cuda_runtime.h>
#include <cuda_bf16.h>
#include <math.h>
#include <stdint.h>

// ---------------- problem constants ----------------
#define NQ 1024
#define ND 200000
#define NF 64
#define NK 32
#define NC 16
#define NH 128

#define MT 128           // queries per CTA
#define NT 128           // points per smem stage
#define NSL 55           // main-pass slices -> grid (8,55)=440 CTAs = one occ-3 wave
#define MAIN_TILES 29    // 55*29*128 = 204160 >= 200000
#define NDPAD 204160
#define SN 16384         // sample size (R10 value — validated)
#define SAMPLE_SLICES 32
#define SAMPLE_TILES 4   // 32*4*128 = 16384
#define CAP 4096
#define MARGIN 4.0f      // mma approx + bf16-store safety margin
#define BIGV 3.0e38f

// ---------------- static device scratch ----------------
__device__ float          g_xxp[NDPAD];
__device__ __nv_bfloat16  g_Xb[(size_t)NDPAD * NF];
__device__ __nv_bfloat16  g_Qb[(size_t)NQ * NF];
__device__ unsigned short g_Du[(size_t)NQ * SN];   // bf16 sample scores
__device__ float          g_tau[NQ];
__device__ int            g_cnt[NQ];
__device__ int            g_si[(size_t)NQ * CAP];
__device__ int            g_topk[NQ * NK];

// ---------------- helpers ----------------
__device__ __forceinline__ uint32_t smem_u32(const void* p) {
    uint32_t a;
    asm("{ .reg .u64 t; cvta.to.shared.u64 t, %1; cvt.u32.u64 %0, t; }" : "=r"(a) : "l"(p));
    return a;
}
#define SWZ128(o) ((o) ^ (((o) >> 3) & 0x70))

__device__ __forceinline__ void cpa16(uint32_t d, const void* s) {
    asm volatile("cp.async.cg.shared.global [%0], [%1], 16;" :: "r"(d), "l"(s) : "memory");
}
#define CPA_COMMIT() asm volatile("cp.async.commit_group;" ::: "memory")
#define CPA_WAIT1()  asm volatile("cp.async.wait_group 1;" ::: "memory")

__device__ __forceinline__ void ldsm4(uint32_t* r, uint32_t a) {
    asm volatile("ldmatrix.sync.aligned.m8n8.x4.shared.b16 {%0,%1,%2,%3}, [%4];"
                 : "=r"(r[0]), "=r"(r[1]), "=r"(r[2]), "=r"(r[3]) : "r"(a));
}
__device__ __forceinline__ void mma16816(float* d, const uint32_t* a, const uint32_t* b) {
    asm volatile(
        "mma.sync.aligned.m16n8k16.row.col.f32.bf16.bf16.f32 "
        "{%0,%1,%2,%3}, {%4,%5,%6,%7}, {%8,%9}, {%0,%1,%2,%3};"
        : "+f"(d[0]), "+f"(d[1]), "+f"(d[2]), "+f"(d[3])
        : "r"(a[0]), "r"(a[1]), "r"(a[2]), "r"(a[3]), "r"(b[0]), "r"(b[1]));
}
__device__ __forceinline__ unsigned short f2bf(float v) {
    __nv_bfloat16 h = __float2bfloat16(v);
    return *(unsigned short*)&h;
}

// ---------------- smem layout (bytes) ----------------
// Q: 16KB, X stages: 3 x 16KB, norms: 3 x 512B, tau: 512B
#define SMQ     0
#define SMX(s)  (16384 + (s) * 16384)
#define SMXX(s) (65536 + (s) * 512)
#define SMTAU   67072
#define SM_TOTAL 67584

// ============================================================
// prep_x: exact fp32 norms + bf16 conversion + padding
// ============================================================
__global__ void prep_x_kernel(const float* __restrict__ Xd) {
    int r = blockIdx.x * 64 + (threadIdx.x >> 2);
    int part = threadIdx.x & 3;
    if (r >= NDPAD) return;
    uint4* dst = (uint4*)(g_Xb + (size_t)r * NF) + part * 2;
    if (r < ND) {
        const float4* row = (const float4*)(Xd + (size_t)r * NF) + part * 4;
        float4 v[4];
        float s = 0.f;
#pragma unroll
        for (int l = 0; l < 4; l++) {
            v[l] = row[l];
            s += v[l].x * v[l].x + v[l].y * v[l].y + v[l].z * v[l].z + v[l].w * v[l].w;
        }
        s += __shfl_xor_sync(0xffffffffu, s, 1);
        s += __shfl_xor_sync(0xffffffffu, s, 2);
        if (part == 0) g_xxp[r] = s;
        unsigned u[8];
#pragma unroll
        for (int l = 0; l < 4; l++) {
            __nv_bfloat162 h0 = __floats2bfloat162_rn(v[l].x, v[l].y);
            __nv_bfloat162 h1 = __floats2bfloat162_rn(v[l].z, v[l].w);
            u[l * 2]     = *(unsigned*)&h0;
            u[l * 2 + 1] = *(unsigned*)&h1;
        }
        dst[0] = make_uint4(u[0], u[1], u[2], u[3]);
        dst[1] = make_uint4(u[4], u[5], u[6], u[7]);
    } else {
        if (part == 0) g_xxp[r] = BIGV;
        uint4 z = make_uint4(0, 0, 0, 0);
        dst[0] = z; dst[1] = z;
    }
}

// prep_q: g_Qb = bf16(-2 * x); also zeroes g_cnt (fused)
__global__ void prep_q_kernel(const float* __restrict__ xq) {
    int i = blockIdx.x * 256 + threadIdx.x;
    float2 v = ((const float2*)xq)[i];
    __nv_bfloat162 h = __floats2bfloat162_rn(-2.f * v.x, -2.f * v.y);
    ((__nv_bfloat162*)g_Qb)[i] = h;
    if (i < NQ) g_cnt[i] = 0;
}

// ============================================================
// MMA kernel: warp tile 32q x 32n (4x2 warp grid), CTA 128q x 128n/stage,
// 3-stage cp.async ring, one __syncthreads per stage, occ 3.
// A (Q) fragments hoisted for the whole slice (32 regs).
// MODE 0: write bf16 approx scores of sample region to g_Du
// MODE 1: filter vs g_tau (min-tree fast path), append survivors
// ============================================================
template <int MODE, int NTILES>
__global__ void __launch_bounds__(256, 3)
mma_kernel() {
    extern __shared__ char smem[];
    const uint32_t sb = smem_u32(smem);
    const int tid = threadIdx.x;
    const int lane = tid & 31;
    const int wid = tid >> 5;
    const int mtile = blockIdx.x;
    const int base = blockIdx.y * NTILES * NT;

    // load Q tile into swizzled smem (128 rows x 128B)
    {
        const uint4* qsrc = (const uint4*)(g_Qb + (size_t)mtile * MT * NF);
#pragma unroll
        for (int c = 0; c < 4; c++) {
            int ch = tid + c * 256;
            int row = ch >> 3, col = ch & 7;
            *(uint4*)(smem + SMQ + SWZ128(row * 128 + col * 16)) = qsrc[ch];
        }
    }
    if (MODE == 1 && tid < MT) ((float*)(smem + SMTAU))[tid] = g_tau[mtile * MT + tid];

    // prologue: issue stages 0 and 1
#pragma unroll
    for (int s = 0; s < 2; s++) {
        if (s < NTILES) {
            const uint4* xs = (const uint4*)(g_Xb + (size_t)(base + s * NT) * NF);
#pragma unroll
            for (int c = 0; c < 4; c++) {
                int ch = tid + c * 256;
                int row = ch >> 3, col = ch & 7;
                cpa16(sb + SMX(s) + SWZ128(row * 128 + col * 16), xs + ch);
            }
            if (tid < 32) cpa16(sb + SMXX(s) + tid * 16, g_xxp + base + s * NT + tid * 4);
        }
        CPA_COMMIT();
    }
    __syncthreads();   // Q (and tau) visible

    const int wr = wid >> 1;          // 0..3 : q-row block of 32
    const int wc = wid & 1;           // 0..1 : n-col block of 32 (within a 64 half)
    const int m0 = wr * 32;
    const int nb = wc * 32;
    const int tq = lane >> 2;         // row within 8
    const int tn2 = (lane & 3) * 2;   // col pair within 8

    // ldmatrix lane addressing
    const int a_row = lane & 15, a_kh = lane >> 4;
    const int b_row = (lane & 7) | ((lane >> 4) << 3), b_kh = (lane >> 3) & 1;

    // hoist A (Q) fragments: [ks][mf*4 + i]  (32 regs)
    uint32_t afr[4][8];
#pragma unroll
    for (int ks = 0; ks < 4; ks++)
#pragma unroll
        for (int mf = 0; mf < 2; mf++) {
            uint32_t addr = sb + SMQ +
                SWZ128((m0 + mf * 16 + a_row) * 128 + ks * 32 + a_kh * 16);
            ldsm4(&afr[ks][mf * 4], addr);
        }

    // per-thread taus (rows: mf in {0,1}, h in {0,1}) + tmax for fast path
    float tr[4], tmax = -BIGV;
    if (MODE == 1) {
        const float* tsm = (const float*)(smem + SMTAU);
#pragma unroll
        for (int mf = 0; mf < 2; mf++)
#pragma unroll
            for (int h = 0; h < 2; h++) {
                tr[mf * 2 + h] = tsm[m0 + mf * 16 + h * 8 + tq];
                tmax = fmaxf(tmax, tr[mf * 2 + h]);
            }
    }

    for (int t = 0; t < NTILES; t++) {
        const int t0 = base + t * NT;
        const int st = t % 3;
        const uint32_t xb  = SMX(st);
        const uint32_t xxb = SMXX(st);

        CPA_WAIT1();          // stage t complete (only stage t+1 may be pending)
        __syncthreads();      // all warps done with stage (t+2)%3's previous life

        // issue prefetch of stage t+2 (after the barrier -> no overwrite hazard)
        if (t + 2 < NTILES) {
            const int ps = (t + 2) % 3;
            const uint4* xs = (const uint4*)(g_Xb + (size_t)(t0 + 2 * NT) * NF);
#pragma unroll
            for (int c = 0; c < 4; c++) {
                int ch = tid + c * 256;
                int row = ch >> 3, col = ch & 7;
                cpa16(sb + SMX(ps) + SWZ128(row * 128 + col * 16), xs + ch);
            }
            if (tid < 32) cpa16(sb + SMXX(ps) + tid * 16, g_xxp + t0 + 2 * NT + tid * 4);
        }
        CPA_COMMIT();         // always commit to keep group count uniform

        // compute the 128-point stage as two 64-col halves
#pragma unroll
        for (int half = 0; half < 2; half++) {
            const int nh = half * 64 + nb;     // n-offset within stage (0..127)

            float d[2][4][4];
#pragma unroll
            for (int i = 0; i < 2; i++)
#pragma unroll
                for (int j = 0; j < 4; j++)
#pragma unroll
                    for (int k = 0; k < 4; k++) d[i][j][k] = 0.f;

#pragma unroll
            for (int ks = 0; ks < 4; ks++) {
                uint32_t b[4][2];
#pragma unroll
                for (int h = 0; h < 2; h++) {
                    uint32_t r[4];
                    uint32_t addr = sb + xb +
                        SWZ128((nh + h * 16 + b_row) * 128 + ks * 32 + b_kh * 16);
                    ldsm4(r, addr);
                    b[h * 2][0] = r[0]; b[h * 2][1] = r[1];
                    b[h * 2 + 1][0] = r[2]; b[h * 2 + 1][1] = r[3];
                }
#pragma unroll
                for (int mf = 0; mf < 2; mf++)
#pragma unroll
                    for (int nf = 0; nf < 4; nf++)
                        mma16816(d[mf][nf], &afr[ks][mf * 4], b[nf]);
            }

            // epilogue for this half: add ||X||^2, then fast-path filter
            const float* xxs = (const float*)(smem + xxb);
            float2 xv[4];
#pragma unroll
            for (int nf = 0; nf < 4; nf++) xv[nf] = *(const float2*)(xxs + nh + nf * 8 + tn2);

            float vmin = BIGV;
#pragma unroll
            for (int mf = 0; mf < 2; mf++)
#pragma unroll
                for (int nf = 0; nf < 4; nf++) {
                    d[mf][nf][0] += xv[nf].x;
                    d[mf][nf][1] += xv[nf].y;
                    d[mf][nf][2] += xv[nf].x;
                    d[mf][nf][3] += xv[nf].y;
                    if (MODE == 1)
                        vmin = fminf(vmin, fminf(fminf(d[mf][nf][0], d[mf][nf][1]),
                                                 fminf(d[mf][nf][2], d[mf][nf][3])));
                }

            if (MODE == 0) {
#pragma unroll
                for (int mf = 0; mf < 2; mf++)
#pragma unroll
                    for (int h = 0; h < 2; h++) {
                        const int gq = mtile * MT + m0 + mf * 16 + h * 8 + tq;
                        unsigned short* dst = g_Du + (size_t)gq * SN + (t0 + nh + tn2);
#pragma unroll
                        for (int nf = 0; nf < 4; nf++) {
                            unsigned short u0 = f2bf(d[mf][nf][h * 2]);
                            unsigned short u1 = f2bf(d[mf][nf][h * 2 + 1]);
                            *(unsigned*)(dst + nf * 8) = (unsigned)u0 | ((unsigned)u1 << 16);
                        }
                    }
            } else if (vmin <= tmax) {   // rare slow path (~1e-3 of thread-tiles)
#pragma unroll
                for (int mf = 0; mf < 2; mf++)
#pragma unroll
                    for (int h = 0; h < 2; h++) {
                        const int gq = mtile * MT + m0 + mf * 16 + h * 8 + tq;
                        const float tau = tr[mf * 2 + h];
#pragma unroll
                        for (int nf = 0; nf < 4; nf++) {
                            float v0 = d[mf][nf][h * 2];
                            float v1 = d[mf][nf][h * 2 + 1];
                            if (v0 <= tau) {
                                int pos = atomicAdd(&g_cnt[gq], 1);
                                if (pos < CAP) g_si[(size_t)gq * CAP + pos] = t0 + nh + nf * 8 + tn2;
                            }
                            if (v1 <= tau) {
                                int pos = atomicAdd(&g_cnt[gq], 1);
                                if (pos < CAP) g_si[(size_t)gq * CAP + pos] = t0 + nh + nf * 8 + tn2 + 1;
                            }
                        }
                    }
            }
        }
    }
}

// ============================================================
// tau: radix-select 32nd smallest bf16 sample score + margin
// 8 warp-private histograms to kill smem-atomic serialization.
// ============================================================
__global__ void tau_kernel() {
    __shared__ unsigned short sU[SN];        // 32KB
    __shared__ unsigned hist[8][256];        // 8KB
    __shared__ unsigned s_prefix;
    __shared__ int s_rank;
    const int b = blockIdx.x, tid = threadIdx.x;
    const int w = tid >> 5;

    for (int i = tid; i < SN / 2; i += 256) {
        unsigned v = ((const unsigned*)(g_Du + (size_t)b * SN))[i];
        unsigned short u0 = (unsigned short)v, u1 = (unsigned short)(v >> 16);
        u0 = (u0 & 0x8000u) ? (unsigned short)~u0 : (unsigned short)(u0 | 0x8000u);
        u1 = (u1 & 0x8000u) ? (unsigned short)~u1 : (unsigned short)(u1 | 0x8000u);
        ((unsigned*)sU)[i] = (unsigned)u0 | ((unsigned)u1 << 16);
    }
    if (tid == 0) { s_prefix = 0u; s_rank = NK; }
    __syncthreads();

#pragma unroll
    for (int lev = 0; lev < 2; lev++) {
        const int sh = 8 - 8 * lev;
#pragma unroll
        for (int j = 0; j < 8; j++) hist[j][tid] = 0;
        __syncthreads();
        const unsigned pfx = s_prefix;
        for (int i = tid; i < SN; i += 256) {
            unsigned u = sU[i];
            if (lev == 0 || (u & 0xFF00u) == pfx)
                atomicAdd(&hist[w][(u >> sh) & 255u], 1u);
        }
        __syncthreads();
        // reduce 8 warp hists into hist[0]
        unsigned tot = hist[0][tid];
#pragma unroll
        for (int j = 1; j < 8; j++) tot += hist[j][tid];
        hist[0][tid] = tot;
        __syncthreads();
        if (tid == 0) {
            int r = s_rank;
            unsigned cum = 0;
            for (int k = 0; k < 256; k++) {
                unsigned h = hist[0][k];
                if (cum + h >= (unsigned)r) {
                    s_rank = r - (int)cum;
                    s_prefix = pfx | ((unsigned)k << sh);
                    break;
                }
                cum += h;
            }
        }
        __syncthreads();
    }
    if (tid == 0) {
        unsigned short u = (unsigned short)s_prefix;
        unsigned short bb = (u & 0x8000u) ? (unsigned short)(u ^ 0x8000u) : (unsigned short)~u;
        g_tau[b] = __uint_as_float((unsigned)bb << 16) + MARGIN;
    }
}

// ============================================================
// rescore + select fused: exact fp32 scores into smem, then
// exact top-32 with (val, idx) tie-break. One block per query.
// ============================================================
__global__ void rsel_kernel(const float* __restrict__ xq, const float* __restrict__ Xd) {
    __shared__ float sv[CAP];
    __shared__ int si[CAP];
    __shared__ float xs[NF];
    __shared__ float rv[8];
    __shared__ int ri[8], rp[8];
    const int b = blockIdx.x, tid = threadIdx.x;
    const int w = tid >> 5, lane = tid & 31;

    if (tid < NF) xs[tid] = xq[(size_t)b * NF + tid];
    int c = g_cnt[b]; if (c > CAP) c = CAP;
    const int cpad = (c + 255) & ~255;
    for (int i = tid; i < cpad; i += 256) { sv[i] = BIGV; si[i] = 0x7FFFFFFF; }
    __syncthreads();

    // exact rescore (warp per survivor)
    float2 xv = *(const float2*)(xs + 2 * lane);
    for (int s = w; s < c; s += 8) {
        int n = g_si[(size_t)b * CAP + s];
        float2 Xv = *(const float2*)(Xd + (size_t)n * NF + 2 * lane);
        float p = xv.x * Xv.x + xv.y * Xv.y;
#pragma unroll
        for (int off = 16; off > 0; off >>= 1) p += __shfl_xor_sync(0xffffffffu, p, off);
        if (lane == 0) { sv[s] = g_xxp[n] - 2.f * p; si[s] = n; }
    }
    __syncthreads();

    // exact top-32 selection
    for (int r = 0; r < NK; r++) {
        float bv = BIGV; int bi = 0x7FFFFFFF; int bp = 0;
        for (int i = tid; i < cpad; i += 256) {
            float v = sv[i]; int ix = si[i];
            if (v < bv || (v == bv && ix < bi)) { bv = v; bi = ix; bp = i; }
        }
#pragma unroll
        for (int off = 16; off > 0; off >>= 1) {
            float ov = __shfl_down_sync(0xffffffffu, bv, off);
            int oi = __shfl_down_sync(0xffffffffu, bi, off);
            int op = __shfl_down_sync(0xffffffffu, bp, off);
            if (ov < bv || (ov == bv && oi < bi)) { bv = ov; bi = oi; bp = op; }
        }
        if (lane == 0) { rv[w] = bv; ri[w] = bi; rp[w] = bp; }
        __syncthreads();
        if (tid == 0) {
            for (int wi = 1; wi < 8; wi++)
                if (rv[wi] < rv[0] || (rv[wi] == rv[0] && ri[wi] < ri[0])) {
                    rv[0] = rv[wi]; ri[0] = ri[wi]; rp[0] = rp[wi];
                }
            g_topk[b * NK + r] = ri[0];
            sv[rp[0]] = BIGV; si[rp[0]] = 0x7FFFFFFF;
        }
        __syncthreads();
    }
}

// ============================================================
// mlp: gather neighbors + gated MLP head (one block per query)
// ============================================================
__global__ void mlp_kernel(const float* __restrict__ xq, const float* __restrict__ Xd,
                           const float* __restrict__ yv, const float* __restrict__ Wg,
                           const float* __restrict__ bg, const float* __restrict__ W1,
                           const float* __restrict__ b1, const float* __restrict__ Wl,
                           const float* __restrict__ bl, float* __restrict__ out) {
    __shared__ float nfs[NK * 65];
    __shared__ float Wgs[65 * NC];
    __shared__ float gs[NK * NC];
    __shared__ float xa[NF + NC];
    __shared__ float red[4];
    __shared__ int idx[NK];
    const int b = blockIdx.x, tid = threadIdx.x;

    if (tid < NK) idx[tid] = g_topk[b * NK + tid];
    for (int i = tid; i < 65 * NC; i += 128) Wgs[i] = Wg[i];
    __syncthreads();
    for (int i = tid; i < NK * NF; i += 128) {
        int k = i >> 6, f = i & 63;
        nfs[k * 65 + f] = Xd[(size_t)idx[k] * NF + f];
    }
    if (tid < NK) nfs[tid * 65 + 64] = yv[idx[tid]];
    __syncthreads();

    {
        int k = tid & 31, c0 = (tid >> 5) * 4;
        float a0 = bg[c0], a1 = bg[c0 + 1], a2 = bg[c0 + 2], a3 = bg[c0 + 3];
#pragma unroll 5
        for (int j = 0; j < 65; j++) {
            float v = nfs[k * 65 + j];
            a0 += v * Wgs[j * NC + c0];
            a1 += v * Wgs[j * NC + c0 + 1];
            a2 += v * Wgs[j * NC + c0 + 2];
            a3 += v * Wgs[j * NC + c0 + 3];
        }
        gs[k * NC + c0] = tanhf(a0);
        gs[k * NC + c0 + 1] = tanhf(a1);
        gs[k * NC + c0 + 2] = tanhf(a2);
        gs[k * NC + c0 + 3] = tanhf(a3);
    }
    __syncthreads();
    if (tid < NF) {
        xa[tid] = xq[(size_t)b * NF + tid];
    } else if (tid < NF + NC) {
        int c = tid - NF;
        float s = 0.f;
#pragma unroll
        for (int k = 0; k < NK; k++) s += gs[k * NC + c];
        xa[tid] = s;
    }
    __syncthreads();

    float s = b1[tid];
#pragma unroll 8
    for (int i = 0; i < NF + NC; i++) s += xa[i] * W1[i * NH + tid];
    float oh = tanhf(s);
    float r = oh * Wl[tid];
#pragma unroll
    for (int off = 16; off > 0; off >>= 1) r += __shfl_down_sync(0xffffffffu, r, off);
    if ((tid & 31) == 0) red[tid >> 5] = r;
    __syncthreads();
    if (tid == 0) {
        float t = red[0] + red[1] + red[2] + red[3] + bl[0];
        out[b] = 1.f / (1.f + expf(-t));
    }
}

// ============================================================
extern "C" void kernel_launch(void* const* d_in, const int* in_sizes, int n_in,
                              void* d_out, int out_size) {
    (void)in_sizes; (void)n_in; (void)out_size;
    const float* xq = (const float*)d_in[0];
    const float* Xd = (const float*)d_in[1];
    const float* yv = (const float*)d_in[2];
    const float* Wg = (const float*)d_in[3];
    const float* bg = (const float*)d_in[4];
    const float* W1 = (const float*)d_in[5];
    const float* b1 = (const float*)d_in[6];
    const float* Wl = (const float*)d_in[7];
    const float* bl = (const float*)d_in[8];
    float* out = (float*)d_out;

    cudaFuncSetAttribute(mma_kernel<0, SAMPLE_TILES>, cudaFuncAttributeMaxDynamicSharedMemorySize, SM_TOTAL);
    cudaFuncSetAttribute(mma_kernel<1, MAIN_TILES>, cudaFuncAttributeMaxDynamicSharedMemorySize, SM_TOTAL);

    prep_x_kernel<<<NDPAD / 64, 256>>>(Xd);
    prep_q_kernel<<<128, 256>>>(xq);
    mma_kernel<0, SAMPLE_TILES><<<dim3(NQ / MT, SAMPLE_SLICES), 256, SM_TOTAL>>>();
    tau_kernel<<<NQ, 256>>>();
    mma_kernel<1, MAIN_TILES><<<dim3(NQ / MT, NSL), 256, SM_TOTAL>>>();
    rsel_kernel<<<NQ, 256>>>(xq, Xd);
    mlp_kernel<<<NQ, 128>>>(xq, Xd, yv, Wg, bg, W1, b1, Wl, bl, out);
}

// round 13
// speedup vs baseline: 1.3089x; 1.0072x over previous
#include <cuda_runtime.h>
#include <cuda_bf16.h>
#include <math.h>
#include <stdint.h>

// ---------------- problem constants ----------------
#define NQ 1024
#define ND 200000
#define NF 64
#define NK 32
#define NC 16
#define NH 128

#define MT 128           // queries per CTA
#define NT 128           // points per smem stage
#define NSL 55           // main-pass slices -> grid (8,55)=440 CTAs = one occ-3 wave
#define MAIN_TILES 29    // 55*29*128 = 204160 >= 200000
#define NDPAD 204160
#define SN 16384         // sample size
#define SAMPLE_SLICES 32
#define SAMPLE_TILES 4   // 32*4*128 = 16384
#define CAP 4096
#define MARGIN 4.0f      // mma approx + bf16-store safety margin
#define BIGV 3.0e38f

// ---------------- static device scratch ----------------
__device__ float          g_xxp[NDPAD];
__device__ __nv_bfloat16  g_Xb[(size_t)NDPAD * NF];
__device__ __nv_bfloat16  g_Qb[(size_t)NQ * NF];
__device__ unsigned short g_Du[(size_t)NQ * SN];   // bf16 sample scores
__device__ float          g_tau[NQ];
__device__ int            g_cnt[NQ];
__device__ int            g_si[(size_t)NQ * CAP];
__device__ int            g_topk[NQ * NK];

// ---------------- helpers ----------------
__device__ __forceinline__ uint32_t smem_u32(const void* p) {
    uint32_t a;
    asm("{ .reg .u64 t; cvta.to.shared.u64 t, %1; cvt.u32.u64 %0, t; }" : "=r"(a) : "l"(p));
    return a;
}
#define SWZ128(o) ((o) ^ (((o) >> 3) & 0x70))

__device__ __forceinline__ void cpa16(uint32_t d, const void* s) {
    asm volatile("cp.async.cg.shared.global [%0], [%1], 16;" :: "r"(d), "l"(s) : "memory");
}
#define CPA_COMMIT() asm volatile("cp.async.commit_group;" ::: "memory")
#define CPA_WAIT1()  asm volatile("cp.async.wait_group 1;" ::: "memory")

__device__ __forceinline__ void ldsm4(uint32_t* r, uint32_t a) {
    asm volatile("ldmatrix.sync.aligned.m8n8.x4.shared.b16 {%0,%1,%2,%3}, [%4];"
                 : "=r"(r[0]), "=r"(r[1]), "=r"(r[2]), "=r"(r[3]) : "r"(a));
}
__device__ __forceinline__ void mma16816(float* d, const uint32_t* a, const uint32_t* b) {
    asm volatile(
        "mma.sync.aligned.m16n8k16.row.col.f32.bf16.bf16.f32 "
        "{%0,%1,%2,%3}, {%4,%5,%6,%7}, {%8,%9}, {%0,%1,%2,%3};"
        : "+f"(d[0]), "+f"(d[1]), "+f"(d[2]), "+f"(d[3])
        : "r"(a[0]), "r"(a[1]), "r"(a[2]), "r"(a[3]), "r"(b[0]), "r"(b[1]));
}
__device__ __forceinline__ unsigned short f2bf(float v) {
    __nv_bfloat16 h = __float2bfloat16(v);
    return *(unsigned short*)&h;
}
// monotonic transform of two packed bf16 keys
__device__ __forceinline__ unsigned key2(unsigned v) {
    unsigned short u0 = (unsigned short)v, u1 = (unsigned short)(v >> 16);
    u0 = (u0 & 0x8000u) ? (unsigned short)~u0 : (unsigned short)(u0 | 0x8000u);
    u1 = (u1 & 0x8000u) ? (unsigned short)~u1 : (unsigned short)(u1 | 0x8000u);
    return (unsigned)u0 | ((unsigned)u1 << 16);
}

// ---------------- smem layout of MMA kernel (bytes) ----------------
#define SMQ     0
#define SMX(s)  (16384 + (s) * 16384)
#define SMXX(s) (65536 + (s) * 512)
#define SMTAU   67072
#define SM_TOTAL 67584

// ============================================================
// prep_x: exact fp32 norms + bf16 conversion + padding
// ============================================================
__global__ void prep_x_kernel(const float* __restrict__ Xd) {
    int r = blockIdx.x * 64 + (threadIdx.x >> 2);
    int part = threadIdx.x & 3;
    if (r >= NDPAD) return;
    uint4* dst = (uint4*)(g_Xb + (size_t)r * NF) + part * 2;
    if (r < ND) {
        const float4* row = (const float4*)(Xd + (size_t)r * NF) + part * 4;
        float4 v[4];
        float s = 0.f;
#pragma unroll
        for (int l = 0; l < 4; l++) {
            v[l] = row[l];
            s += v[l].x * v[l].x + v[l].y * v[l].y + v[l].z * v[l].z + v[l].w * v[l].w;
        }
        s += __shfl_xor_sync(0xffffffffu, s, 1);
        s += __shfl_xor_sync(0xffffffffu, s, 2);
        if (part == 0) g_xxp[r] = s;
        unsigned u[8];
#pragma unroll
        for (int l = 0; l < 4; l++) {
            __nv_bfloat162 h0 = __floats2bfloat162_rn(v[l].x, v[l].y);
            __nv_bfloat162 h1 = __floats2bfloat162_rn(v[l].z, v[l].w);
            u[l * 2]     = *(unsigned*)&h0;
            u[l * 2 + 1] = *(unsigned*)&h1;
        }
        dst[0] = make_uint4(u[0], u[1], u[2], u[3]);
        dst[1] = make_uint4(u[4], u[5], u[6], u[7]);
    } else {
        if (part == 0) g_xxp[r] = BIGV;
        uint4 z = make_uint4(0, 0, 0, 0);
        dst[0] = z; dst[1] = z;
    }
}

// prep_q: g_Qb = bf16(-2 * x); also zeroes g_cnt (fused)
__global__ void prep_q_kernel(const float* __restrict__ xq) {
    int i = blockIdx.x * 256 + threadIdx.x;
    float2 v = ((const float2*)xq)[i];
    __nv_bfloat162 h = __floats2bfloat162_rn(-2.f * v.x, -2.f * v.y);
    ((__nv_bfloat162*)g_Qb)[i] = h;
    if (i < NQ) g_cnt[i] = 0;
}

// ============================================================
// MMA kernel: warp tile 32q x 32n (4x2 warp grid), CTA 128q x 128n/stage,
// 3-stage cp.async ring, one __syncthreads per stage, occ 3.
// A (Q) fragments hoisted for the whole slice (32 regs).
// MODE 0: write bf16 approx scores of sample region to g_Du
// MODE 1: filter vs g_tau (min-tree fast path), append survivors
// ============================================================
template <int MODE, int NTILES>
__global__ void __launch_bounds__(256, 3)
mma_kernel() {
    extern __shared__ char smem[];
    const uint32_t sb = smem_u32(smem);
    const int tid = threadIdx.x;
    const int lane = tid & 31;
    const int wid = tid >> 5;
    const int mtile = blockIdx.x;
    const int base = blockIdx.y * NTILES * NT;

    // load Q tile into swizzled smem (128 rows x 128B)
    {
        const uint4* qsrc = (const uint4*)(g_Qb + (size_t)mtile * MT * NF);
#pragma unroll
        for (int c = 0; c < 4; c++) {
            int ch = tid + c * 256;
            int row = ch >> 3, col = ch & 7;
            *(uint4*)(smem + SMQ + SWZ128(row * 128 + col * 16)) = qsrc[ch];
        }
    }
    if (MODE == 1 && tid < MT) ((float*)(smem + SMTAU))[tid] = g_tau[mtile * MT + tid];

    // prologue: issue stages 0 and 1
#pragma unroll
    for (int s = 0; s < 2; s++) {
        if (s < NTILES) {
            const uint4* xs = (const uint4*)(g_Xb + (size_t)(base + s * NT) * NF);
#pragma unroll
            for (int c = 0; c < 4; c++) {
                int ch = tid + c * 256;
                int row = ch >> 3, col = ch & 7;
                cpa16(sb + SMX(s) + SWZ128(row * 128 + col * 16), xs + ch);
            }
            if (tid < 32) cpa16(sb + SMXX(s) + tid * 16, g_xxp + base + s * NT + tid * 4);
        }
        CPA_COMMIT();
    }
    __syncthreads();   // Q (and tau) visible

    const int wr = wid >> 1;          // 0..3 : q-row block of 32
    const int wc = wid & 1;           // 0..1 : n-col block of 32 (within a 64 half)
    const int m0 = wr * 32;
    const int nb = wc * 32;
    const int tq = lane >> 2;         // row within 8
    const int tn2 = (lane & 3) * 2;   // col pair within 8

    // ldmatrix lane addressing
    const int a_row = lane & 15, a_kh = lane >> 4;
    const int b_row = (lane & 7) | ((lane >> 4) << 3), b_kh = (lane >> 3) & 1;

    // hoist A (Q) fragments: [ks][mf*4 + i]  (32 regs)
    uint32_t afr[4][8];
#pragma unroll
    for (int ks = 0; ks < 4; ks++)
#pragma unroll
        for (int mf = 0; mf < 2; mf++) {
            uint32_t addr = sb + SMQ +
                SWZ128((m0 + mf * 16 + a_row) * 128 + ks * 32 + a_kh * 16);
            ldsm4(&afr[ks][mf * 4], addr);
        }

    // per-thread taus (rows: mf in {0,1}, h in {0,1}) + tmax for fast path
    float tr[4], tmax = -BIGV;
    if (MODE == 1) {
        const float* tsm = (const float*)(smem + SMTAU);
#pragma unroll
        for (int mf = 0; mf < 2; mf++)
#pragma unroll
            for (int h = 0; h < 2; h++) {
                tr[mf * 2 + h] = tsm[m0 + mf * 16 + h * 8 + tq];
                tmax = fmaxf(tmax, tr[mf * 2 + h]);
            }
    }

    for (int t = 0; t < NTILES; t++) {
        const int t0 = base + t * NT;
        const int st = t % 3;
        const uint32_t xb  = SMX(st);
        const uint32_t xxb = SMXX(st);

        CPA_WAIT1();          // stage t complete (only stage t+1 may be pending)
        __syncthreads();      // all warps done with stage (t+2)%3's previous life

        // issue prefetch of stage t+2 (after the barrier -> no overwrite hazard)
        if (t + 2 < NTILES) {
            const int ps = (t + 2) % 3;
            const uint4* xs = (const uint4*)(g_Xb + (size_t)(t0 + 2 * NT) * NF);
#pragma unroll
            for (int c = 0; c < 4; c++) {
                int ch = tid + c * 256;
                int row = ch >> 3, col = ch & 7;
                cpa16(sb + SMX(ps) + SWZ128(row * 128 + col * 16), xs + ch);
            }
            if (tid < 32) cpa16(sb + SMXX(ps) + tid * 16, g_xxp + t0 + 2 * NT + tid * 4);
        }
        CPA_COMMIT();         // always commit to keep group count uniform

        // compute the 128-point stage as two 64-col halves
#pragma unroll
        for (int half = 0; half < 2; half++) {
            const int nh = half * 64 + nb;     // n-offset within stage (0..127)

            float d[2][4][4];
#pragma unroll
            for (int i = 0; i < 2; i++)
#pragma unroll
                for (int j = 0; j < 4; j++)
#pragma unroll
                    for (int k = 0; k < 4; k++) d[i][j][k] = 0.f;

#pragma unroll
            for (int ks = 0; ks < 4; ks++) {
                uint32_t b[4][2];
#pragma unroll
                for (int h = 0; h < 2; h++) {
                    uint32_t r[4];
                    uint32_t addr = sb + xb +
                        SWZ128((nh + h * 16 + b_row) * 128 + ks * 32 + b_kh * 16);
                    ldsm4(r, addr);
                    b[h * 2][0] = r[0]; b[h * 2][1] = r[1];
                    b[h * 2 + 1][0] = r[2]; b[h * 2 + 1][1] = r[3];
                }
#pragma unroll
                for (int mf = 0; mf < 2; mf++)
#pragma unroll
                    for (int nf = 0; nf < 4; nf++)
                        mma16816(d[mf][nf], &afr[ks][mf * 4], b[nf]);
            }

            // epilogue for this half: add ||X||^2, then fast-path filter
            const float* xxs = (const float*)(smem + xxb);
            float2 xv[4];
#pragma unroll
            for (int nf = 0; nf < 4; nf++) xv[nf] = *(const float2*)(xxs + nh + nf * 8 + tn2);

            float vmin = BIGV;
#pragma unroll
            for (int mf = 0; mf < 2; mf++)
#pragma unroll
                for (int nf = 0; nf < 4; nf++) {
                    d[mf][nf][0] += xv[nf].x;
                    d[mf][nf][1] += xv[nf].y;
                    d[mf][nf][2] += xv[nf].x;
                    d[mf][nf][3] += xv[nf].y;
                    if (MODE == 1)
                        vmin = fminf(vmin, fminf(fminf(d[mf][nf][0], d[mf][nf][1]),
                                                 fminf(d[mf][nf][2], d[mf][nf][3])));
                }

            if (MODE == 0) {
#pragma unroll
                for (int mf = 0; mf < 2; mf++)
#pragma unroll
                    for (int h = 0; h < 2; h++) {
                        const int gq = mtile * MT + m0 + mf * 16 + h * 8 + tq;
                        unsigned short* dst = g_Du + (size_t)gq * SN + (t0 + nh + tn2);
#pragma unroll
                        for (int nf = 0; nf < 4; nf++) {
                            unsigned short u0 = f2bf(d[mf][nf][h * 2]);
                            unsigned short u1 = f2bf(d[mf][nf][h * 2 + 1]);
                            *(unsigned*)(dst + nf * 8) = (unsigned)u0 | ((unsigned)u1 << 16);
                        }
                    }
            } else if (vmin <= tmax) {   // rare slow path (~1e-3 of thread-tiles)
#pragma unroll
                for (int mf = 0; mf < 2; mf++)
#pragma unroll
                    for (int h = 0; h < 2; h++) {
                        const int gq = mtile * MT + m0 + mf * 16 + h * 8 + tq;
                        const float tau = tr[mf * 2 + h];
#pragma unroll
                        for (int nf = 0; nf < 4; nf++) {
                            float v0 = d[mf][nf][h * 2];
                            float v1 = d[mf][nf][h * 2 + 1];
                            if (v0 <= tau) {
                                int pos = atomicAdd(&g_cnt[gq], 1);
                                if (pos < CAP) g_si[(size_t)gq * CAP + pos] = t0 + nh + nf * 8 + tn2;
                            }
                            if (v1 <= tau) {
                                int pos = atomicAdd(&g_cnt[gq], 1);
                                if (pos < CAP) g_si[(size_t)gq * CAP + pos] = t0 + nh + nf * 8 + tn2 + 1;
                            }
                        }
                    }
            }
        }
    }
}

// ============================================================
// tau: radix-select 32nd smallest bf16 sample score + margin.
// uint4 (16B) streaming loads -> 4x memory-level parallelism.
// ============================================================
__global__ void tau_kernel() {
    __shared__ unsigned short sU[SN];        // 32KB
    __shared__ unsigned hist[8][256];        // 8KB
    __shared__ unsigned s_prefix;
    __shared__ int s_rank;
    const int b = blockIdx.x, tid = threadIdx.x;
    const int w = tid >> 5;

    // vectorized load + transform: SN/8 = 2048 uint4 chunks
    {
        const uint4* src = (const uint4*)(g_Du + (size_t)b * SN);
        uint4* dst = (uint4*)sU;
#pragma unroll
        for (int c = 0; c < SN / 8 / 256; c++) {
            int i = tid + c * 256;
            uint4 v = src[i];
            v.x = key2(v.x); v.y = key2(v.y); v.z = key2(v.z); v.w = key2(v.w);
            dst[i] = v;
        }
    }
    if (tid == 0) { s_prefix = 0u; s_rank = NK; }
    __syncthreads();

#pragma unroll
    for (int lev = 0; lev < 2; lev++) {
        const int sh = 8 - 8 * lev;
#pragma unroll
        for (int j = 0; j < 8; j++) hist[j][tid] = 0;
        __syncthreads();
        const unsigned pfx = s_prefix;
        for (int i = tid; i < SN; i += 256) {
            unsigned u = sU[i];
            if (lev == 0 || (u & 0xFF00u) == pfx)
                atomicAdd(&hist[w][(u >> sh) & 255u], 1u);
        }
        __syncthreads();
        unsigned tot = hist[0][tid];
#pragma unroll
        for (int j = 1; j < 8; j++) tot += hist[j][tid];
        hist[0][tid] = tot;
        __syncthreads();
        if (tid == 0) {
            int r = s_rank;
            unsigned cum = 0;
            for (int k = 0; k < 256; k++) {
                unsigned h = hist[0][k];
                if (cum + h >= (unsigned)r) {
                    s_rank = r - (int)cum;
                    s_prefix = pfx | ((unsigned)k << sh);
                    break;
                }
                cum += h;
            }
        }
        __syncthreads();
    }
    if (tid == 0) {
        unsigned short u = (unsigned short)s_prefix;
        unsigned short bb = (u & 0x8000u) ? (unsigned short)(u ^ 0x8000u) : (unsigned short)~u;
        g_tau[b] = __uint_as_float((unsigned)bb << 16) + MARGIN;
    }
}

// ============================================================
// rescore + select fused: exact fp32 scores into smem, then
// exact top-32 with (val, idx) tie-break. One block per query.
// ============================================================
__global__ void rsel_kernel(const float* __restrict__ xq, const float* __restrict__ Xd) {
    __shared__ float sv[CAP];
    __shared__ int si[CAP];
    __shared__ float xs[NF];
    __shared__ float rv[8];
    __shared__ int ri[8], rp[8];
    const int b = blockIdx.x, tid = threadIdx.x;
    const int w = tid >> 5, lane = tid & 31;

    if (tid < NF) xs[tid] = xq[(size_t)b * NF + tid];
    int c = g_cnt[b]; if (c > CAP) c = CAP;
    const int cpad = (c + 255) & ~255;
    for (int i = tid; i < cpad; i += 256) { sv[i] = BIGV; si[i] = 0x7FFFFFFF; }
    __syncthreads();

    // exact rescore (warp per survivor)
    float2 xv = *(const float2*)(xs + 2 * lane);
    for (int s = w; s < c; s += 8) {
        int n = g_si[(size_t)b * CAP + s];
        float2 Xv = *(const float2*)(Xd + (size_t)n * NF + 2 * lane);
        float p = xv.x * Xv.x + xv.y * Xv.y;
#pragma unroll
        for (int off = 16; off > 0; off >>= 1) p += __shfl_xor_sync(0xffffffffu, p, off);
        if (lane == 0) { sv[s] = g_xxp[n] - 2.f * p; si[s] = n; }
    }
    __syncthreads();

    // exact top-32 selection
    for (int r = 0; r < NK; r++) {
        float bv = BIGV; int bi = 0x7FFFFFFF; int bp = 0;
        for (int i = tid; i < cpad; i += 256) {
            float v = sv[i]; int ix = si[i];
            if (v < bv || (v == bv && ix < bi)) { bv = v; bi = ix; bp = i; }
        }
#pragma unroll
        for (int off = 16; off > 0; off >>= 1) {
            float ov = __shfl_down_sync(0xffffffffu, bv, off);
            int oi = __shfl_down_sync(0xffffffffu, bi, off);
            int op = __shfl_down_sync(0xffffffffu, bp, off);
            if (ov < bv || (ov == bv && oi < bi)) { bv = ov; bi = oi; bp = op; }
        }
        if (lane == 0) { rv[w] = bv; ri[w] = bi; rp[w] = bp; }
        __syncthreads();
        if (tid == 0) {
            for (int wi = 1; wi < 8; wi++)
                if (rv[wi] < rv[0] || (rv[wi] == rv[0] && ri[wi] < ri[0])) {
                    rv[0] = rv[wi]; ri[0] = ri[wi]; rp[0] = rp[wi];
                }
            g_topk[b * NK + r] = ri[0];
            sv[rp[0]] = BIGV; si[rp[0]] = 0x7FFFFFFF;
        }
        __syncthreads();
    }
}

// ============================================================
// mlp: gather neighbors + gated MLP head.
// 2 queries per 256-thread block (sub-blocks of 128).
// ============================================================
__global__ void mlp_kernel(const float* __restrict__ xq, const float* __restrict__ Xd,
                           const float* __restrict__ yv, const float* __restrict__ Wg,
                           const float* __restrict__ bg, const float* __restrict__ W1,
                           const float* __restrict__ b1, const float* __restrict__ Wl,
                           const float* __restrict__ bl, float* __restrict__ out) {
    __shared__ float nfs[2][NK * 65];
    __shared__ float Wgs[65 * NC];
    __shared__ float gs[2][NK * NC];
    __shared__ float xa[2][NF + NC];
    __shared__ float red[2][4];
    __shared__ int idx[2][NK];
    const int sub = threadIdx.x >> 7;        // 0/1: which query
    const int tid = threadIdx.x & 127;
    const int b = blockIdx.x * 2 + sub;

    if (tid < NK) idx[sub][tid] = g_topk[b * NK + tid];
    for (int i = threadIdx.x; i < 65 * NC; i += 256) Wgs[i] = Wg[i];
    __syncthreads();
    for (int i = tid; i < NK * NF; i += 128) {
        int k = i >> 6, f = i & 63;
        nfs[sub][k * 65 + f] = Xd[(size_t)idx[sub][k] * NF + f];
    }
    if (tid < NK) nfs[sub][tid * 65 + 64] = yv[idx[sub][tid]];
    __syncthreads();

    {
        int k = tid & 31, c0 = (tid >> 5) * 4;
        float a0 = bg[c0], a1 = bg[c0 + 1], a2 = bg[c0 + 2], a3 = bg[c0 + 3];
#pragma unroll 5
        for (int j = 0; j < 65; j++) {
            float v = nfs[sub][k * 65 + j];
            a0 += v * Wgs[j * NC + c0];
            a1 += v * Wgs[j * NC + c0 + 1];
            a2 += v * Wgs[j * NC + c0 + 2];
            a3 += v * Wgs[j * NC + c0 + 3];
        }
        gs[sub][k * NC + c0] = tanhf(a0);
        gs[sub][k * NC + c0 + 1] = tanhf(a1);
        gs[sub][k * NC + c0 + 2] = tanhf(a2);
        gs[sub][k * NC + c0 + 3] = tanhf(a3);
    }
    __syncthreads();
    if (tid < NF) {
        xa[sub][tid] = xq[(size_t)b * NF + tid];
    } else if (tid < NF + NC) {
        int c = tid - NF;
        float s = 0.f;
#pragma unroll
        for (int k = 0; k < NK; k++) s += gs[sub][k * NC + c];
        xa[sub][tid] = s;
    }
    __syncthreads();

    float s = b1[tid];
#pragma unroll 8
    for (int i = 0; i < NF + NC; i++) s += xa[sub][i] * W1[i * NH + tid];
    float oh = tanhf(s);
    float r = oh * Wl[tid];
#pragma unroll
    for (int off = 16; off > 0; off >>= 1) r += __shfl_down_sync(0xffffffffu, r, off);
    if ((tid & 31) == 0) red[sub][tid >> 5] = r;
    __syncthreads();
    if (tid == 0) {
        float t = red[sub][0] + red[sub][1] + red[sub][2] + red[sub][3] + bl[0];
        out[b] = 1.f / (1.f + expf(-t));
    }
}

// ============================================================
extern "C" void kernel_launch(void* const* d_in, const int* in_sizes, int n_in,
                              void* d_out, int out_size) {
    (void)in_sizes; (void)n_in; (void)out_size;
    const float* xq = (const float*)d_in[0];
    const float* Xd = (const float*)d_in[1];
    const float* yv = (const float*)d_in[2];
    const float* Wg = (const float*)d_in[3];
    const float* bg = (const float*)d_in[4];
    const float* W1 = (const float*)d_in[5];
    const float* b1 = (const float*)d_in[6];
    const float* Wl = (const float*)d_in[7];
    const float* bl = (const float*)d_in[8];
    float* out = (float*)d_out;

    cudaFuncSetAttribute(mma_kernel<0, SAMPLE_TILES>, cudaFuncAttributeMaxDynamicSharedMemorySize, SM_TOTAL);
    cudaFuncSetAttribute(mma_kernel<1, MAIN_TILES>, cudaFuncAttributeMaxDynamicSharedMemorySize, SM_TOTAL);

    prep_x_kernel<<<NDPAD / 64, 256>>>(Xd);
    prep_q_kernel<<<128, 256>>>(xq);
    mma_kernel<0, SAMPLE_TILES><<<dim3(NQ / MT, SAMPLE_SLICES), 256, SM_TOTAL>>>();
    tau_kernel<<<NQ, 256>>>();
    mma_kernel<1, MAIN_TILES><<<dim3(NQ / MT, NSL), 256, SM_TOTAL>>>();
    rsel_kernel<<<NQ, 256>>>(xq, Xd);
    mlp_kernel<<<NQ / 2, 256>>>(xq, Xd, yv, Wg, bg, W1, b1, Wl, bl, out);
}

// round 14
// speedup vs baseline: 1.3251x; 1.0124x over previous
#include <cuda_runtime.h>
#include <cuda_bf16.h>
#include <math.h>
#include <stdint.h>

// ---------------- problem constants ----------------
#define NQ 1024
#define ND 200000
#define NF 64
#define NK 32
#define NC 16
#define NH 128

#define MT 128           // queries per CTA
#define NT 128           // points per smem stage
#define NSL 55           // main-pass slices -> grid (8,55)=440 CTAs = one occ-3 wave
#define MAIN_TILES 29    // 55*29*128 = 204160 >= 200000
#define NDPAD 204160
#define SN 16384         // sample size
#define SAMPLE_SLICES 32
#define SAMPLE_TILES 4   // 32*4*128 = 16384
#define CAP 4096
#define MARGIN 4.0f      // mma approx + bf16-store safety margin
#define BIGV 3.0e38f

// ---------------- static device scratch ----------------
__device__ float          g_xxp[NDPAD];
__device__ __nv_bfloat16  g_Xb[(size_t)NDPAD * NF];
__device__ __nv_bfloat16  g_Qb[(size_t)NQ * NF];
__device__ unsigned short g_Du[(size_t)NQ * SN];   // bf16 sample scores
__device__ float          g_tau[NQ];
__device__ int            g_cnt[NQ];
__device__ int            g_si[(size_t)NQ * CAP];
__device__ int            g_topk[NQ * NK];

// ---------------- helpers ----------------
__device__ __forceinline__ uint32_t smem_u32(const void* p) {
    uint32_t a;
    asm("{ .reg .u64 t; cvta.to.shared.u64 t, %1; cvt.u32.u64 %0, t; }" : "=r"(a) : "l"(p));
    return a;
}
#define SWZ128(o) ((o) ^ (((o) >> 3) & 0x70))

__device__ __forceinline__ void cpa16(uint32_t d, const void* s) {
    asm volatile("cp.async.cg.shared.global [%0], [%1], 16;" :: "r"(d), "l"(s) : "memory");
}
#define CPA_COMMIT() asm volatile("cp.async.commit_group;" ::: "memory")
#define CPA_WAIT1()  asm volatile("cp.async.wait_group 1;" ::: "memory")

__device__ __forceinline__ void ldsm4(uint32_t* r, uint32_t a) {
    asm volatile("ldmatrix.sync.aligned.m8n8.x4.shared.b16 {%0,%1,%2,%3}, [%4];"
                 : "=r"(r[0]), "=r"(r[1]), "=r"(r[2]), "=r"(r[3]) : "r"(a));
}
__device__ __forceinline__ void mma16816(float* d, const uint32_t* a, const uint32_t* b) {
    asm volatile(
        "mma.sync.aligned.m16n8k16.row.col.f32.bf16.bf16.f32 "
        "{%0,%1,%2,%3}, {%4,%5,%6,%7}, {%8,%9}, {%0,%1,%2,%3};"
        : "+f"(d[0]), "+f"(d[1]), "+f"(d[2]), "+f"(d[3])
        : "r"(a[0]), "r"(a[1]), "r"(a[2]), "r"(a[3]), "r"(b[0]), "r"(b[1]));
}
__device__ __forceinline__ unsigned short f2bf(float v) {
    __nv_bfloat16 h = __float2bfloat16(v);
    return *(unsigned short*)&h;
}
// monotonic transform of two packed bf16 keys
__device__ __forceinline__ unsigned key2(unsigned v) {
    unsigned short u0 = (unsigned short)v, u1 = (unsigned short)(v >> 16);
    u0 = (u0 & 0x8000u) ? (unsigned short)~u0 : (unsigned short)(u0 | 0x8000u);
    u1 = (u1 & 0x8000u) ? (unsigned short)~u1 : (unsigned short)(u1 | 0x8000u);
    return (unsigned)u0 | ((unsigned)u1 << 16);
}

// ---------------- smem layout of MMA kernel (bytes) ----------------
#define SMQ     0
#define SMX(s)  (16384 + (s) * 16384)
#define SMXX(s) (65536 + (s) * 512)
#define SMTAU   67072
#define SM_TOTAL 67584

// ============================================================
// prep_x: exact fp32 norms + bf16 conversion + padding
// ============================================================
__global__ void prep_x_kernel(const float* __restrict__ Xd) {
    int r = blockIdx.x * 64 + (threadIdx.x >> 2);
    int part = threadIdx.x & 3;
    if (r >= NDPAD) return;
    uint4* dst = (uint4*)(g_Xb + (size_t)r * NF) + part * 2;
    if (r < ND) {
        const float4* row = (const float4*)(Xd + (size_t)r * NF) + part * 4;
        float4 v[4];
        float s = 0.f;
#pragma unroll
        for (int l = 0; l < 4; l++) {
            v[l] = row[l];
            s += v[l].x * v[l].x + v[l].y * v[l].y + v[l].z * v[l].z + v[l].w * v[l].w;
        }
        s += __shfl_xor_sync(0xffffffffu, s, 1);
        s += __shfl_xor_sync(0xffffffffu, s, 2);
        if (part == 0) g_xxp[r] = s;
        unsigned u[8];
#pragma unroll
        for (int l = 0; l < 4; l++) {
            __nv_bfloat162 h0 = __floats2bfloat162_rn(v[l].x, v[l].y);
            __nv_bfloat162 h1 = __floats2bfloat162_rn(v[l].z, v[l].w);
            u[l * 2]     = *(unsigned*)&h0;
            u[l * 2 + 1] = *(unsigned*)&h1;
        }
        dst[0] = make_uint4(u[0], u[1], u[2], u[3]);
        dst[1] = make_uint4(u[4], u[5], u[6], u[7]);
    } else {
        if (part == 0) g_xxp[r] = BIGV;
        uint4 z = make_uint4(0, 0, 0, 0);
        dst[0] = z; dst[1] = z;
    }
}

// prep_q: g_Qb = bf16(-2 * x); also zeroes g_cnt (fused)
__global__ void prep_q_kernel(const float* __restrict__ xq) {
    int i = blockIdx.x * 256 + threadIdx.x;
    float2 v = ((const float2*)xq)[i];
    __nv_bfloat162 h = __floats2bfloat162_rn(-2.f * v.x, -2.f * v.y);
    ((__nv_bfloat162*)g_Qb)[i] = h;
    if (i < NQ) g_cnt[i] = 0;
}

// ============================================================
// MMA kernel: warp tile 32q x 32n (4x2 warp grid), CTA 128q x 128n/stage,
// 3-stage cp.async ring, one __syncthreads per stage, occ 3.
// A (Q) fragments hoisted for the whole slice (32 regs).
// MODE 0: write bf16 approx scores of sample region to g_Du
// MODE 1: filter vs g_tau (min-tree fast path), append survivors
// ============================================================
template <int MODE, int NTILES>
__global__ void __launch_bounds__(256, 3)
mma_kernel() {
    extern __shared__ char smem[];
    const uint32_t sb = smem_u32(smem);
    const int tid = threadIdx.x;
    const int lane = tid & 31;
    const int wid = tid >> 5;
    const int mtile = blockIdx.x;
    const int base = blockIdx.y * NTILES * NT;

    // load Q tile into swizzled smem (128 rows x 128B)
    {
        const uint4* qsrc = (const uint4*)(g_Qb + (size_t)mtile * MT * NF);
#pragma unroll
        for (int c = 0; c < 4; c++) {
            int ch = tid + c * 256;
            int row = ch >> 3, col = ch & 7;
            *(uint4*)(smem + SMQ + SWZ128(row * 128 + col * 16)) = qsrc[ch];
        }
    }
    if (MODE == 1 && tid < MT) ((float*)(smem + SMTAU))[tid] = g_tau[mtile * MT + tid];

    // prologue: issue stages 0 and 1
#pragma unroll
    for (int s = 0; s < 2; s++) {
        if (s < NTILES) {
            const uint4* xs = (const uint4*)(g_Xb + (size_t)(base + s * NT) * NF);
#pragma unroll
            for (int c = 0; c < 4; c++) {
                int ch = tid + c * 256;
                int row = ch >> 3, col = ch & 7;
                cpa16(sb + SMX(s) + SWZ128(row * 128 + col * 16), xs + ch);
            }
            if (tid < 32) cpa16(sb + SMXX(s) + tid * 16, g_xxp + base + s * NT + tid * 4);
        }
        CPA_COMMIT();
    }
    __syncthreads();   // Q (and tau) visible

    const int wr = wid >> 1;          // 0..3 : q-row block of 32
    const int wc = wid & 1;           // 0..1 : n-col block of 32 (within a 64 half)
    const int m0 = wr * 32;
    const int nb = wc * 32;
    const int tq = lane >> 2;         // row within 8
    const int tn2 = (lane & 3) * 2;   // col pair within 8

    // ldmatrix lane addressing
    const int a_row = lane & 15, a_kh = lane >> 4;
    const int b_row = (lane & 7) | ((lane >> 4) << 3), b_kh = (lane >> 3) & 1;

    // hoist A (Q) fragments: [ks][mf*4 + i]  (32 regs)
    uint32_t afr[4][8];
#pragma unroll
    for (int ks = 0; ks < 4; ks++)
#pragma unroll
        for (int mf = 0; mf < 2; mf++) {
            uint32_t addr = sb + SMQ +
                SWZ128((m0 + mf * 16 + a_row) * 128 + ks * 32 + a_kh * 16);
            ldsm4(&afr[ks][mf * 4], addr);
        }

    // per-thread taus (rows: mf in {0,1}, h in {0,1}) + tmax for fast path
    float tr[4], tmax = -BIGV;
    if (MODE == 1) {
        const float* tsm = (const float*)(smem + SMTAU);
#pragma unroll
        for (int mf = 0; mf < 2; mf++)
#pragma unroll
            for (int h = 0; h < 2; h++) {
                tr[mf * 2 + h] = tsm[m0 + mf * 16 + h * 8 + tq];
                tmax = fmaxf(tmax, tr[mf * 2 + h]);
            }
    }

    for (int t = 0; t < NTILES; t++) {
        const int t0 = base + t * NT;
        const int st = t % 3;
        const uint32_t xb  = SMX(st);
        const uint32_t xxb = SMXX(st);

        CPA_WAIT1();          // stage t complete (only stage t+1 may be pending)
        __syncthreads();      // all warps done with stage (t+2)%3's previous life

        // issue prefetch of stage t+2 (after the barrier -> no overwrite hazard)
        if (t + 2 < NTILES) {
            const int ps = (t + 2) % 3;
            const uint4* xs = (const uint4*)(g_Xb + (size_t)(t0 + 2 * NT) * NF);
#pragma unroll
            for (int c = 0; c < 4; c++) {
                int ch = tid + c * 256;
                int row = ch >> 3, col = ch & 7;
                cpa16(sb + SMX(ps) + SWZ128(row * 128 + col * 16), xs + ch);
            }
            if (tid < 32) cpa16(sb + SMXX(ps) + tid * 16, g_xxp + t0 + 2 * NT + tid * 4);
        }
        CPA_COMMIT();         // always commit to keep group count uniform

        // compute the 128-point stage as two 64-col halves
#pragma unroll
        for (int half = 0; half < 2; half++) {
            const int nh = half * 64 + nb;     // n-offset within stage (0..127)

            float d[2][4][4];
#pragma unroll
            for (int i = 0; i < 2; i++)
#pragma unroll
                for (int j = 0; j < 4; j++)
#pragma unroll
                    for (int k = 0; k < 4; k++) d[i][j][k] = 0.f;

#pragma unroll
            for (int ks = 0; ks < 4; ks++) {
                uint32_t b[4][2];
#pragma unroll
                for (int h = 0; h < 2; h++) {
                    uint32_t r[4];
                    uint32_t addr = sb + xb +
                        SWZ128((nh + h * 16 + b_row) * 128 + ks * 32 + b_kh * 16);
                    ldsm4(r, addr);
                    b[h * 2][0] = r[0]; b[h * 2][1] = r[1];
                    b[h * 2 + 1][0] = r[2]; b[h * 2 + 1][1] = r[3];
                }
#pragma unroll
                for (int mf = 0; mf < 2; mf++)
#pragma unroll
                    for (int nf = 0; nf < 4; nf++)
                        mma16816(d[mf][nf], &afr[ks][mf * 4], b[nf]);
            }

            // epilogue for this half: add ||X||^2, then fast-path filter
            const float* xxs = (const float*)(smem + xxb);
            float2 xv[4];
#pragma unroll
            for (int nf = 0; nf < 4; nf++) xv[nf] = *(const float2*)(xxs + nh + nf * 8 + tn2);

            float vmin = BIGV;
#pragma unroll
            for (int mf = 0; mf < 2; mf++)
#pragma unroll
                for (int nf = 0; nf < 4; nf++) {
                    d[mf][nf][0] += xv[nf].x;
                    d[mf][nf][1] += xv[nf].y;
                    d[mf][nf][2] += xv[nf].x;
                    d[mf][nf][3] += xv[nf].y;
                    if (MODE == 1)
                        vmin = fminf(vmin, fminf(fminf(d[mf][nf][0], d[mf][nf][1]),
                                                 fminf(d[mf][nf][2], d[mf][nf][3])));
                }

            if (MODE == 0) {
#pragma unroll
                for (int mf = 0; mf < 2; mf++)
#pragma unroll
                    for (int h = 0; h < 2; h++) {
                        const int gq = mtile * MT + m0 + mf * 16 + h * 8 + tq;
                        unsigned short* dst = g_Du + (size_t)gq * SN + (t0 + nh + tn2);
#pragma unroll
                        for (int nf = 0; nf < 4; nf++) {
                            unsigned short u0 = f2bf(d[mf][nf][h * 2]);
                            unsigned short u1 = f2bf(d[mf][nf][h * 2 + 1]);
                            *(unsigned*)(dst + nf * 8) = (unsigned)u0 | ((unsigned)u1 << 16);
                        }
                    }
            } else if (vmin <= tmax) {   // rare slow path (~1e-3 of thread-tiles)
#pragma unroll
                for (int mf = 0; mf < 2; mf++)
#pragma unroll
                    for (int h = 0; h < 2; h++) {
                        const int gq = mtile * MT + m0 + mf * 16 + h * 8 + tq;
                        const float tau = tr[mf * 2 + h];
#pragma unroll
                        for (int nf = 0; nf < 4; nf++) {
                            float v0 = d[mf][nf][h * 2];
                            float v1 = d[mf][nf][h * 2 + 1];
                            if (v0 <= tau) {
                                int pos = atomicAdd(&g_cnt[gq], 1);
                                if (pos < CAP) g_si[(size_t)gq * CAP + pos] = t0 + nh + nf * 8 + tn2;
                            }
                            if (v1 <= tau) {
                                int pos = atomicAdd(&g_cnt[gq], 1);
                                if (pos < CAP) g_si[(size_t)gq * CAP + pos] = t0 + nh + nf * 8 + tn2 + 1;
                            }
                        }
                    }
            }
        }
    }
}

// ============================================================
// tau: radix-select 32nd smallest bf16 sample score + margin.
// TWO PASSES over g_Du from global (no smem staging):
// pass 1 histograms the high key byte (DRAM/L2 stream),
// pass 2 re-reads (L1/L2-hot) and histograms the low byte.
// smem = 8KB hist only -> high occupancy.
// ============================================================
__global__ void tau_kernel() {
    __shared__ unsigned hist[8][256];        // 8KB
    __shared__ unsigned s_prefix;
    __shared__ int s_rank;
    const int b = blockIdx.x, tid = threadIdx.x;
    const int w = tid >> 5;
    const uint4* src = (const uint4*)(g_Du + (size_t)b * SN);

    // ---- pass 1: high byte ----
#pragma unroll
    for (int j = 0; j < 8; j++) hist[j][tid] = 0;
    __syncthreads();
#pragma unroll
    for (int c = 0; c < SN / 8 / 256; c++) {
        uint4 v = src[tid + c * 256];
        unsigned k0 = key2(v.x), k1 = key2(v.y), k2 = key2(v.z), k3 = key2(v.w);
        atomicAdd(&hist[w][(k0 >> 8) & 255u], 1u);
        atomicAdd(&hist[w][(k0 >> 24) & 255u], 1u);
        atomicAdd(&hist[w][(k1 >> 8) & 255u], 1u);
        atomicAdd(&hist[w][(k1 >> 24) & 255u], 1u);
        atomicAdd(&hist[w][(k2 >> 8) & 255u], 1u);
        atomicAdd(&hist[w][(k2 >> 24) & 255u], 1u);
        atomicAdd(&hist[w][(k3 >> 8) & 255u], 1u);
        atomicAdd(&hist[w][(k3 >> 24) & 255u], 1u);
    }
    __syncthreads();
    {
        unsigned tot = hist[0][tid];
#pragma unroll
        for (int j = 1; j < 8; j++) tot += hist[j][tid];
        hist[0][tid] = tot;
    }
    __syncthreads();
    if (tid == 0) {
        int r = NK;
        unsigned cum = 0;
        for (int k = 0; k < 256; k++) {
            unsigned h = hist[0][k];
            if (cum + h >= (unsigned)r) { s_rank = r - (int)cum; s_prefix = (unsigned)k << 8; break; }
            cum += h;
        }
    }
    __syncthreads();
    const unsigned pfx = s_prefix;

    // ---- pass 2: low byte among keys whose high byte matches ----
#pragma unroll
    for (int j = 0; j < 8; j++) hist[j][tid] = 0;
    __syncthreads();
#pragma unroll
    for (int c = 0; c < SN / 8 / 256; c++) {
        uint4 v = src[tid + c * 256];
        unsigned ks[4] = {key2(v.x), key2(v.y), key2(v.z), key2(v.w)};
#pragma unroll
        for (int e = 0; e < 4; e++) {
            unsigned lo = ks[e] & 0xFFFFu, hi = ks[e] >> 16;
            if ((lo & 0xFF00u) == pfx) atomicAdd(&hist[w][lo & 255u], 1u);
            if ((hi & 0xFF00u) == pfx) atomicAdd(&hist[w][hi & 255u], 1u);
        }
    }
    __syncthreads();
    {
        unsigned tot = hist[0][tid];
#pragma unroll
        for (int j = 1; j < 8; j++) tot += hist[j][tid];
        hist[0][tid] = tot;
    }
    __syncthreads();
    if (tid == 0) {
        int r = s_rank;
        unsigned cum = 0;
        unsigned key = pfx;
        for (int k = 0; k < 256; k++) {
            unsigned h = hist[0][k];
            if (cum + h >= (unsigned)r) { key = pfx | (unsigned)k; break; }
            cum += h;
        }
        unsigned short u = (unsigned short)key;
        unsigned short bb = (u & 0x8000u) ? (unsigned short)(u ^ 0x8000u) : (unsigned short)~u;
        g_tau[b] = __uint_as_float((unsigned)bb << 16) + MARGIN;
    }
}

// ============================================================
// rescore + select fused: exact fp32 scores into smem, then
// exact top-32 with (val, idx) tie-break. One block per query.
// ============================================================
__global__ void rsel_kernel(const float* __restrict__ xq, const float* __restrict__ Xd) {
    __shared__ float sv[CAP];
    __shared__ int si[CAP];
    __shared__ float xs[NF];
    __shared__ float rv[8];
    __shared__ int ri[8], rp[8];
    const int b = blockIdx.x, tid = threadIdx.x;
    const int w = tid >> 5, lane = tid & 31;

    if (tid < NF) xs[tid] = xq[(size_t)b * NF + tid];
    int c = g_cnt[b]; if (c > CAP) c = CAP;
    const int cpad = (c + 255) & ~255;
    for (int i = tid; i < cpad; i += 256) { sv[i] = BIGV; si[i] = 0x7FFFFFFF; }
    __syncthreads();

    // exact rescore (warp per survivor)
    float2 xv = *(const float2*)(xs + 2 * lane);
    for (int s = w; s < c; s += 8) {
        int n = g_si[(size_t)b * CAP + s];
        float2 Xv = *(const float2*)(Xd + (size_t)n * NF + 2 * lane);
        float p = xv.x * Xv.x + xv.y * Xv.y;
#pragma unroll
        for (int off = 16; off > 0; off >>= 1) p += __shfl_xor_sync(0xffffffffu, p, off);
        if (lane == 0) { sv[s] = g_xxp[n] - 2.f * p; si[s] = n; }
    }
    __syncthreads();

    // exact top-32 selection
    for (int r = 0; r < NK; r++) {
        float bv = BIGV; int bi = 0x7FFFFFFF; int bp = 0;
        for (int i = tid; i < cpad; i += 256) {
            float v = sv[i]; int ix = si[i];
            if (v < bv || (v == bv && ix < bi)) { bv = v; bi = ix; bp = i; }
        }
#pragma unroll
        for (int off = 16; off > 0; off >>= 1) {
            float ov = __shfl_down_sync(0xffffffffu, bv, off);
            int oi = __shfl_down_sync(0xffffffffu, bi, off);
            int op = __shfl_down_sync(0xffffffffu, bp, off);
            if (ov < bv || (ov == bv && oi < bi)) { bv = ov; bi = oi; bp = op; }
        }
        if (lane == 0) { rv[w] = bv; ri[w] = bi; rp[w] = bp; }
        __syncthreads();
        if (tid == 0) {
            for (int wi = 1; wi < 8; wi++)
                if (rv[wi] < rv[0] || (rv[wi] == rv[0] && ri[wi] < ri[0])) {
                    rv[0] = rv[wi]; ri[0] = ri[wi]; rp[0] = rp[wi];
                }
            g_topk[b * NK + r] = ri[0];
            sv[rp[0]] = BIGV; si[rp[0]] = 0x7FFFFFFF;
        }
        __syncthreads();
    }
}

// ============================================================
// mlp: gather neighbors + gated MLP head.
// 2 queries per 256-thread block (sub-blocks of 128).
// ============================================================
__global__ void mlp_kernel(const float* __restrict__ xq, const float* __restrict__ Xd,
                           const float* __restrict__ yv, const float* __restrict__ Wg,
                           const float* __restrict__ bg, const float* __restrict__ W1,
                           const float* __restrict__ b1, const float* __restrict__ Wl,
                           const float* __restrict__ bl, float* __restrict__ out) {
    __shared__ float nfs[2][NK * 65];
    __shared__ float Wgs[65 * NC];
    __shared__ float gs[2][NK * NC];
    __shared__ float xa[2][NF + NC];
    __shared__ float red[2][4];
    __shared__ int idx[2][NK];
    const int sub = threadIdx.x >> 7;        // 0/1: which query
    const int tid = threadIdx.x & 127;
    const int b = blockIdx.x * 2 + sub;

    if (tid < NK) idx[sub][tid] = g_topk[b * NK + tid];
    for (int i = threadIdx.x; i < 65 * NC; i += 256) Wgs[i] = Wg[i];
    __syncthreads();
    for (int i = tid; i < NK * NF; i += 128) {
        int k = i >> 6, f = i & 63;
        nfs[sub][k * 65 + f] = Xd[(size_t)idx[sub][k] * NF + f];
    }
    if (tid < NK) nfs[sub][tid * 65 + 64] = yv[idx[sub][tid]];
    __syncthreads();

    {
        int k = tid & 31, c0 = (tid >> 5) * 4;
        float a0 = bg[c0], a1 = bg[c0 + 1], a2 = bg[c0 + 2], a3 = bg[c0 + 3];
#pragma unroll 5
        for (int j = 0; j < 65; j++) {
            float v = nfs[sub][k * 65 + j];
            a0 += v * Wgs[j * NC + c0];
            a1 += v * Wgs[j * NC + c0 + 1];
            a2 += v * Wgs[j * NC + c0 + 2];
            a3 += v * Wgs[j * NC + c0 + 3];
        }
        gs[sub][k * NC + c0] = tanhf(a0);
        gs[sub][k * NC + c0 + 1] = tanhf(a1);
        gs[sub][k * NC + c0 + 2] = tanhf(a2);
        gs[sub][k * NC + c0 + 3] = tanhf(a3);
    }
    __syncthreads();
    if (tid < NF) {
        xa[sub][tid] = xq[(size_t)b * NF + tid];
    } else if (tid < NF + NC) {
        int c = tid - NF;
        float s = 0.f;
#pragma unroll
        for (int k = 0; k < NK; k++) s += gs[sub][k * NC + c];
        xa[sub][tid] = s;
    }
    __syncthreads();

    float s = b1[tid];
#pragma unroll 8
    for (int i = 0; i < NF + NC; i++) s += xa[sub][i] * W1[i * NH + tid];
    float oh = tanhf(s);
    float r = oh * Wl[tid];
#pragma unroll
    for (int off = 16; off > 0; off >>= 1) r += __shfl_down_sync(0xffffffffu, r, off);
    if ((tid & 31) == 0) red[sub][tid >> 5] = r;
    __syncthreads();
    if (tid == 0) {
        float t = red[sub][0] + red[sub][1] + red[sub][2] + red[sub][3] + bl[0];
        out[b] = 1.f / (1.f + expf(-t));
    }
}

// ============================================================
extern "C" void kernel_launch(void* const* d_in, const int* in_sizes, int n_in,
                              void* d_out, int out_size) {
    (void)in_sizes; (void)n_in; (void)out_size;
    const float* xq = (const float*)d_in[0];
    const float* Xd = (const float*)d_in[1];
    const float* yv = (const float*)d_in[2];
    const float* Wg = (const float*)d_in[3];
    const float* bg = (const float*)d_in[4];
    const float* W1 = (const float*)d_in[5];
    const float* b1 = (const float*)d_in[6];
    const float* Wl = (const float*)d_in[7];
    const float* bl = (const float*)d_in[8];
    float* out = (float*)d_out;

    cudaFuncSetAttribute(mma_kernel<0, SAMPLE_TILES>, cudaFuncAttributeMaxDynamicSharedMemorySize, SM_TOTAL);
    cudaFuncSetAttribute(mma_kernel<1, MAIN_TILES>, cudaFuncAttributeMaxDynamicSharedMemorySize, SM_TOTAL);

    prep_x_kernel<<<NDPAD / 64, 256>>>(Xd);
    prep_q_kernel<<<128, 256>>>(xq);
    mma_kernel<0, SAMPLE_TILES><<<dim3(NQ / MT, SAMPLE_SLICES), 256, SM_TOTAL>>>();
    tau_kernel<<<NQ, 256>>>();
    mma_kernel<1, MAIN_TILES><<<dim3(NQ / MT, NSL), 256, SM_TOTAL>>>();
    rsel_kernel<<<NQ, 256>>>(xq, Xd);
    mlp_kernel<<<NQ / 2, 256>>>(xq, Xd, yv, Wg, bg, W1, b1, Wl, bl, out);
}

// round 15
// speedup vs baseline: 1.3477x; 1.0171x over previous
#include <cuda_runtime.h>
#include <cuda_bf16.h>
#include <math.h>
#include <stdint.h>

// ---------------- problem constants ----------------
#define NQ 1024
#define ND 200000
#define NF 64
#define NK 32
#define NC 16
#define NH 128

#define MT 128           // queries per CTA
#define NT 128           // points per smem stage
#define NSL 55           // main-pass slices -> grid (8,55)=440 CTAs = one occ-3 wave
#define MAIN_TILES 29    // 55*29*128 = 204160 >= 200000
#define NDPAD 204160
#define SN 16384         // sample size
#define SAMPLE_SLICES 32
#define SAMPLE_TILES 4   // 32*4*128 = 16384
#define CAP 4096
#define MARGIN 4.0f      // mma approx + bf16-store safety margin
#define BIGV 3.0e38f

// ---------------- static device scratch ----------------
__device__ float          g_xxp[NDPAD];
__device__ __nv_bfloat16  g_Xb[(size_t)NDPAD * NF];
__device__ __nv_bfloat16  g_Qb[(size_t)NQ * NF];
__device__ unsigned short g_Du[(size_t)NQ * SN];   // radix-transformed bf16 keys
__device__ float          g_tau[NQ];
__device__ int            g_cnt[NQ];
__device__ int            g_si[(size_t)NQ * CAP];
__device__ int            g_topk[NQ * NK];

// ---------------- helpers ----------------
__device__ __forceinline__ uint32_t smem_u32(const void* p) {
    uint32_t a;
    asm("{ .reg .u64 t; cvta.to.shared.u64 t, %1; cvt.u32.u64 %0, t; }" : "=r"(a) : "l"(p));
    return a;
}
#define SWZ128(o) ((o) ^ (((o) >> 3) & 0x70))

__device__ __forceinline__ void cpa16(uint32_t d, const void* s) {
    asm volatile("cp.async.cg.shared.global [%0], [%1], 16;" :: "r"(d), "l"(s) : "memory");
}
#define CPA_COMMIT() asm volatile("cp.async.commit_group;" ::: "memory")
#define CPA_WAIT1()  asm volatile("cp.async.wait_group 1;" ::: "memory")

__device__ __forceinline__ void ldsm4(uint32_t* r, uint32_t a) {
    asm volatile("ldmatrix.sync.aligned.m8n8.x4.shared.b16 {%0,%1,%2,%3}, [%4];"
                 : "=r"(r[0]), "=r"(r[1]), "=r"(r[2]), "=r"(r[3]) : "r"(a));
}
__device__ __forceinline__ void mma16816(float* d, const uint32_t* a, const uint32_t* b) {
    asm volatile(
        "mma.sync.aligned.m16n8k16.row.col.f32.bf16.bf16.f32 "
        "{%0,%1,%2,%3}, {%4,%5,%6,%7}, {%8,%9}, {%0,%1,%2,%3};"
        : "+f"(d[0]), "+f"(d[1]), "+f"(d[2]), "+f"(d[3])
        : "r"(a[0]), "r"(a[1]), "r"(a[2]), "r"(a[3]), "r"(b[0]), "r"(b[1]));
}
__device__ __forceinline__ unsigned short f2bf(float v) {
    __nv_bfloat16 h = __float2bfloat16(v);
    return *(unsigned short*)&h;
}
// bf16 -> monotonic 16-bit radix key (done once, in the GEMM epilogue)
__device__ __forceinline__ unsigned short f2key(float v) {
    unsigned short h = f2bf(v);
    return (h & 0x8000u) ? (unsigned short)~h : (unsigned short)(h | 0x8000u);
}

// ---------------- smem layout of MMA kernel (bytes) ----------------
#define SMQ     0
#define SMX(s)  (16384 + (s) * 16384)
#define SMXX(s) (65536 + (s) * 512)
#define SMTAU   67072
#define SM_TOTAL 67584

// ============================================================
// prep: exact fp32 norms + bf16 X conversion + padding.
// Also (fused) converts Q to bf16(-2x) and zeroes g_cnt.
// ============================================================
__global__ void prep_kernel(const float* __restrict__ Xd, const float* __restrict__ xq) {
    const int gid = blockIdx.x * 256 + threadIdx.x;

    // fused prep_q: 32768 float2 elements
    if (gid < NQ * NF / 2) {
        float2 v = ((const float2*)xq)[gid];
        __nv_bfloat162 h = __floats2bfloat162_rn(-2.f * v.x, -2.f * v.y);
        ((__nv_bfloat162*)g_Qb)[gid] = h;
    }
    if (gid < NQ) g_cnt[gid] = 0;

    int r = blockIdx.x * 64 + (threadIdx.x >> 2);
    int part = threadIdx.x & 3;
    if (r >= NDPAD) return;
    uint4* dst = (uint4*)(g_Xb + (size_t)r * NF) + part * 2;
    if (r < ND) {
        const float4* row = (const float4*)(Xd + (size_t)r * NF) + part * 4;
        float4 v[4];
        float s = 0.f;
#pragma unroll
        for (int l = 0; l < 4; l++) {
            v[l] = row[l];
            s += v[l].x * v[l].x + v[l].y * v[l].y + v[l].z * v[l].z + v[l].w * v[l].w;
        }
        s += __shfl_xor_sync(0xffffffffu, s, 1);
        s += __shfl_xor_sync(0xffffffffu, s, 2);
        if (part == 0) g_xxp[r] = s;
        unsigned u[8];
#pragma unroll
        for (int l = 0; l < 4; l++) {
            __nv_bfloat162 h0 = __floats2bfloat162_rn(v[l].x, v[l].y);
            __nv_bfloat162 h1 = __floats2bfloat162_rn(v[l].z, v[l].w);
            u[l * 2]     = *(unsigned*)&h0;
            u[l * 2 + 1] = *(unsigned*)&h1;
        }
        dst[0] = make_uint4(u[0], u[1], u[2], u[3]);
        dst[1] = make_uint4(u[4], u[5], u[6], u[7]);
    } else {
        if (part == 0) g_xxp[r] = BIGV;
        uint4 z = make_uint4(0, 0, 0, 0);
        dst[0] = z; dst[1] = z;
    }
}

// ============================================================
// MMA kernel: warp tile 32q x 32n (4x2 warp grid), CTA 128q x 128n/stage,
// 3-stage cp.async ring, one __syncthreads per stage, occ 3.
// A (Q) fragments hoisted for the whole slice (32 regs).
// MODE 0: write radix keys of sample-region scores to g_Du
// MODE 1: filter vs g_tau (min-tree fast path), append survivors
// ============================================================
template <int MODE, int NTILES>
__global__ void __launch_bounds__(256, 3)
mma_kernel() {
    extern __shared__ char smem[];
    const uint32_t sb = smem_u32(smem);
    const int tid = threadIdx.x;
    const int lane = tid & 31;
    const int wid = tid >> 5;
    const int mtile = blockIdx.x;
    const int base = blockIdx.y * NTILES * NT;

    // load Q tile into swizzled smem (128 rows x 128B)
    {
        const uint4* qsrc = (const uint4*)(g_Qb + (size_t)mtile * MT * NF);
#pragma unroll
        for (int c = 0; c < 4; c++) {
            int ch = tid + c * 256;
            int row = ch >> 3, col = ch & 7;
            *(uint4*)(smem + SMQ + SWZ128(row * 128 + col * 16)) = qsrc[ch];
        }
    }
    if (MODE == 1 && tid < MT) ((float*)(smem + SMTAU))[tid] = g_tau[mtile * MT + tid];

    // prologue: issue stages 0 and 1
#pragma unroll
    for (int s = 0; s < 2; s++) {
        if (s < NTILES) {
            const uint4* xs = (const uint4*)(g_Xb + (size_t)(base + s * NT) * NF);
#pragma unroll
            for (int c = 0; c < 4; c++) {
                int ch = tid + c * 256;
                int row = ch >> 3, col = ch & 7;
                cpa16(sb + SMX(s) + SWZ128(row * 128 + col * 16), xs + ch);
            }
            if (tid < 32) cpa16(sb + SMXX(s) + tid * 16, g_xxp + base + s * NT + tid * 4);
        }
        CPA_COMMIT();
    }
    __syncthreads();   // Q (and tau) visible

    const int wr = wid >> 1;          // 0..3 : q-row block of 32
    const int wc = wid & 1;           // 0..1 : n-col block of 32 (within a 64 half)
    const int m0 = wr * 32;
    const int nb = wc * 32;
    const int tq = lane >> 2;         // row within 8
    const int tn2 = (lane & 3) * 2;   // col pair within 8

    // ldmatrix lane addressing
    const int a_row = lane & 15, a_kh = lane >> 4;
    const int b_row = (lane & 7) | ((lane >> 4) << 3), b_kh = (lane >> 3) & 1;

    // hoist A (Q) fragments: [ks][mf*4 + i]  (32 regs)
    uint32_t afr[4][8];
#pragma unroll
    for (int ks = 0; ks < 4; ks++)
#pragma unroll
        for (int mf = 0; mf < 2; mf++) {
            uint32_t addr = sb + SMQ +
                SWZ128((m0 + mf * 16 + a_row) * 128 + ks * 32 + a_kh * 16);
            ldsm4(&afr[ks][mf * 4], addr);
        }

    // per-thread taus (rows: mf in {0,1}, h in {0,1}) + tmax for fast path
    float tr[4], tmax = -BIGV;
    if (MODE == 1) {
        const float* tsm = (const float*)(smem + SMTAU);
#pragma unroll
        for (int mf = 0; mf < 2; mf++)
#pragma unroll
            for (int h = 0; h < 2; h++) {
                tr[mf * 2 + h] = tsm[m0 + mf * 16 + h * 8 + tq];
                tmax = fmaxf(tmax, tr[mf * 2 + h]);
            }
    }

    for (int t = 0; t < NTILES; t++) {
        const int t0 = base + t * NT;
        const int st = t % 3;
        const uint32_t xb  = SMX(st);
        const uint32_t xxb = SMXX(st);

        CPA_WAIT1();          // stage t complete (only stage t+1 may be pending)
        __syncthreads();      // all warps done with stage (t+2)%3's previous life

        // issue prefetch of stage t+2 (after the barrier -> no overwrite hazard)
        if (t + 2 < NTILES) {
            const int ps = (t + 2) % 3;
            const uint4* xs = (const uint4*)(g_Xb + (size_t)(t0 + 2 * NT) * NF);
#pragma unroll
            for (int c = 0; c < 4; c++) {
                int ch = tid + c * 256;
                int row = ch >> 3, col = ch & 7;
                cpa16(sb + SMX(ps) + SWZ128(row * 128 + col * 16), xs + ch);
            }
            if (tid < 32) cpa16(sb + SMXX(ps) + tid * 16, g_xxp + t0 + 2 * NT + tid * 4);
        }
        CPA_COMMIT();         // always commit to keep group count uniform

        // compute the 128-point stage as two 64-col halves
#pragma unroll
        for (int half = 0; half < 2; half++) {
            const int nh = half * 64 + nb;     // n-offset within stage (0..127)

            float d[2][4][4];
#pragma unroll
            for (int i = 0; i < 2; i++)
#pragma unroll
                for (int j = 0; j < 4; j++)
#pragma unroll
                    for (int k = 0; k < 4; k++) d[i][j][k] = 0.f;

#pragma unroll
            for (int ks = 0; ks < 4; ks++) {
                uint32_t b[4][2];
#pragma unroll
                for (int h = 0; h < 2; h++) {
                    uint32_t r[4];
                    uint32_t addr = sb + xb +
                        SWZ128((nh + h * 16 + b_row) * 128 + ks * 32 + b_kh * 16);
                    ldsm4(r, addr);
                    b[h * 2][0] = r[0]; b[h * 2][1] = r[1];
                    b[h * 2 + 1][0] = r[2]; b[h * 2 + 1][1] = r[3];
                }
#pragma unroll
                for (int mf = 0; mf < 2; mf++)
#pragma unroll
                    for (int nf = 0; nf < 4; nf++)
                        mma16816(d[mf][nf], &afr[ks][mf * 4], b[nf]);
            }

            // epilogue for this half: add ||X||^2, then fast-path filter
            const float* xxs = (const float*)(smem + xxb);
            float2 xv[4];
#pragma unroll
            for (int nf = 0; nf < 4; nf++) xv[nf] = *(const float2*)(xxs + nh + nf * 8 + tn2);

            float vmin = BIGV;
#pragma unroll
            for (int mf = 0; mf < 2; mf++)
#pragma unroll
                for (int nf = 0; nf < 4; nf++) {
                    d[mf][nf][0] += xv[nf].x;
                    d[mf][nf][1] += xv[nf].y;
                    d[mf][nf][2] += xv[nf].x;
                    d[mf][nf][3] += xv[nf].y;
                    if (MODE == 1)
                        vmin = fminf(vmin, fminf(fminf(d[mf][nf][0], d[mf][nf][1]),
                                                 fminf(d[mf][nf][2], d[mf][nf][3])));
                }

            if (MODE == 0) {
#pragma unroll
                for (int mf = 0; mf < 2; mf++)
#pragma unroll
                    for (int h = 0; h < 2; h++) {
                        const int gq = mtile * MT + m0 + mf * 16 + h * 8 + tq;
                        unsigned short* dst = g_Du + (size_t)gq * SN + (t0 + nh + tn2);
#pragma unroll
                        for (int nf = 0; nf < 4; nf++) {
                            unsigned short u0 = f2key(d[mf][nf][h * 2]);
                            unsigned short u1 = f2key(d[mf][nf][h * 2 + 1]);
                            *(unsigned*)(dst + nf * 8) = (unsigned)u0 | ((unsigned)u1 << 16);
                        }
                    }
            } else if (vmin <= tmax) {   // rare slow path (~1e-3 of thread-tiles)
#pragma unroll
                for (int mf = 0; mf < 2; mf++)
#pragma unroll
                    for (int h = 0; h < 2; h++) {
                        const int gq = mtile * MT + m0 + mf * 16 + h * 8 + tq;
                        const float tau = tr[mf * 2 + h];
#pragma unroll
                        for (int nf = 0; nf < 4; nf++) {
                            float v0 = d[mf][nf][h * 2];
                            float v1 = d[mf][nf][h * 2 + 1];
                            if (v0 <= tau) {
                                int pos = atomicAdd(&g_cnt[gq], 1);
                                if (pos < CAP) g_si[(size_t)gq * CAP + pos] = t0 + nh + nf * 8 + tn2;
                            }
                            if (v1 <= tau) {
                                int pos = atomicAdd(&g_cnt[gq], 1);
                                if (pos < CAP) g_si[(size_t)gq * CAP + pos] = t0 + nh + nf * 8 + tn2 + 1;
                            }
                        }
                    }
            }
        }
    }
}

// ============================================================
// tau: radix-select 32nd smallest key + margin.
// Keys are pre-transformed in the GEMM epilogue. Pass 1 streams
// global once into registers + high-byte histogram; pass 2 runs
// entirely from the register cache. smem = 8KB hist only.
// ============================================================
__global__ void tau_kernel() {
    __shared__ unsigned hist[8][256];        // 8KB
    __shared__ unsigned s_prefix;
    __shared__ int s_rank;
    const int b = blockIdx.x, tid = threadIdx.x;
    const int w = tid >> 5;
    const uint4* src = (const uint4*)(g_Du + (size_t)b * SN);

    unsigned kreg[32];                        // 64 keys cached in registers

    // ---- pass 1: load + high-byte histogram ----
#pragma unroll
    for (int j = 0; j < 8; j++) hist[j][tid] = 0;
    __syncthreads();
#pragma unroll
    for (int c = 0; c < 8; c++) {
        uint4 v = src[tid + c * 256];
        kreg[c * 4 + 0] = v.x; kreg[c * 4 + 1] = v.y;
        kreg[c * 4 + 2] = v.z; kreg[c * 4 + 3] = v.w;
#pragma unroll
        for (int e = 0; e < 4; e++) {
            unsigned k = kreg[c * 4 + e];
            atomicAdd(&hist[w][(k >> 8) & 255u], 1u);
            atomicAdd(&hist[w][(k >> 24) & 255u], 1u);
        }
    }
    __syncthreads();
    {
        unsigned tot = hist[0][tid];
#pragma unroll
        for (int j = 1; j < 8; j++) tot += hist[j][tid];
        hist[0][tid] = tot;
    }
    __syncthreads();
    if (tid == 0) {
        int r = NK;
        unsigned cum = 0;
        for (int k = 0; k < 256; k++) {
            unsigned h = hist[0][k];
            if (cum + h >= (unsigned)r) { s_rank = r - (int)cum; s_prefix = (unsigned)k << 8; break; }
            cum += h;
        }
    }
    __syncthreads();
    const unsigned pfx = s_prefix;

    // ---- pass 2: low byte among matching keys, from registers ----
#pragma unroll
    for (int j = 0; j < 8; j++) hist[j][tid] = 0;
    __syncthreads();
#pragma unroll
    for (int i = 0; i < 32; i++) {
        unsigned k = kreg[i];
        unsigned lo = k & 0xFFFFu, hi = k >> 16;
        if ((lo & 0xFF00u) == pfx) atomicAdd(&hist[w][lo & 255u], 1u);
        if ((hi & 0xFF00u) == pfx) atomicAdd(&hist[w][hi & 255u], 1u);
    }
    __syncthreads();
    {
        unsigned tot = hist[0][tid];
#pragma unroll
        for (int j = 1; j < 8; j++) tot += hist[j][tid];
        hist[0][tid] = tot;
    }
    __syncthreads();
    if (tid == 0) {
        int r = s_rank;
        unsigned cum = 0;
        unsigned key = pfx;
        for (int k = 0; k < 256; k++) {
            unsigned h = hist[0][k];
            if (cum + h >= (unsigned)r) { key = pfx | (unsigned)k; break; }
            cum += h;
        }
        unsigned short u = (unsigned short)key;
        unsigned short bb = (u & 0x8000u) ? (unsigned short)(u ^ 0x8000u) : (unsigned short)~u;
        g_tau[b] = __uint_as_float((unsigned)bb << 16) + MARGIN;
    }
}

// ============================================================
// rescore + select fused: exact fp32 scores into smem, then
// exact top-32 with (val, idx) tie-break. One block per query.
// ============================================================
__global__ void rsel_kernel(const float* __restrict__ xq, const float* __restrict__ Xd) {
    __shared__ float sv[CAP];
    __shared__ int si[CAP];
    __shared__ float xs[NF];
    __shared__ float rv[8];
    __shared__ int ri[8], rp[8];
    const int b = blockIdx.x, tid = threadIdx.x;
    const int w = tid >> 5, lane = tid & 31;

    if (tid < NF) xs[tid] = xq[(size_t)b * NF + tid];
    int c = g_cnt[b]; if (c > CAP) c = CAP;
    const int cpad = (c + 255) & ~255;
    for (int i = tid; i < cpad; i += 256) { sv[i] = BIGV; si[i] = 0x7FFFFFFF; }
    __syncthreads();

    // exact rescore (warp per survivor)
    float2 xv = *(const float2*)(xs + 2 * lane);
    for (int s = w; s < c; s += 8) {
        int n = g_si[(size_t)b * CAP + s];
        float2 Xv = *(const float2*)(Xd + (size_t)n * NF + 2 * lane);
        float p = xv.x * Xv.x + xv.y * Xv.y;
#pragma unroll
        for (int off = 16; off > 0; off >>= 1) p += __shfl_xor_sync(0xffffffffu, p, off);
        if (lane == 0) { sv[s] = g_xxp[n] - 2.f * p; si[s] = n; }
    }
    __syncthreads();

    // exact top-32 selection
    for (int r = 0; r < NK; r++) {
        float bv = BIGV; int bi = 0x7FFFFFFF; int bp = 0;
        for (int i = tid; i < cpad; i += 256) {
            float v = sv[i]; int ix = si[i];
            if (v < bv || (v == bv && ix < bi)) { bv = v; bi = ix; bp = i; }
        }
#pragma unroll
        for (int off = 16; off > 0; off >>= 1) {
            float ov = __shfl_down_sync(0xffffffffu, bv, off);
            int oi = __shfl_down_sync(0xffffffffu, bi, off);
            int op = __shfl_down_sync(0xffffffffu, bp, off);
            if (ov < bv || (ov == bv && oi < bi)) { bv = ov; bi = oi; bp = op; }
        }
        if (lane == 0) { rv[w] = bv; ri[w] = bi; rp[w] = bp; }
        __syncthreads();
        if (tid == 0) {
            for (int wi = 1; wi < 8; wi++)
                if (rv[wi] < rv[0] || (rv[wi] == rv[0] && ri[wi] < ri[0])) {
                    rv[0] = rv[wi]; ri[0] = ri[wi]; rp[0] = rp[wi];
                }
            g_topk[b * NK + r] = ri[0];
            sv[rp[0]] = BIGV; si[rp[0]] = 0x7FFFFFFF;
        }
        __syncthreads();
    }
}

// ============================================================
// mlp: gather neighbors + gated MLP head.
// 2 queries per 256-thread block (sub-blocks of 128).
// ============================================================
__global__ void mlp_kernel(const float* __restrict__ xq, const float* __restrict__ Xd,
                           const float* __restrict__ yv, const float* __restrict__ Wg,
                           const float* __restrict__ bg, const float* __restrict__ W1,
                           const float* __restrict__ b1, const float* __restrict__ Wl,
                           const float* __restrict__ bl, float* __restrict__ out) {
    __shared__ float nfs[2][NK * 65];
    __shared__ float Wgs[65 * NC];
    __shared__ float gs[2][NK * NC];
    __shared__ float xa[2][NF + NC];
    __shared__ float red[2][4];
    __shared__ int idx[2][NK];
    const int sub = threadIdx.x >> 7;        // 0/1: which query
    const int tid = threadIdx.x & 127;
    const int b = blockIdx.x * 2 + sub;

    if (tid < NK) idx[sub][tid] = g_topk[b * NK + tid];
    for (int i = threadIdx.x; i < 65 * NC; i += 256) Wgs[i] = Wg[i];
    __syncthreads();
    for (int i = tid; i < NK * NF; i += 128) {
        int k = i >> 6, f = i & 63;
        nfs[sub][k * 65 + f] = Xd[(size_t)idx[sub][k] * NF + f];
    }
    if (tid < NK) nfs[sub][tid * 65 + 64] = yv[idx[sub][tid]];
    __syncthreads();

    {
        int k = tid & 31, c0 = (tid >> 5) * 4;
        float a0 = bg[c0], a1 = bg[c0 + 1], a2 = bg[c0 + 2], a3 = bg[c0 + 3];
#pragma unroll 5
        for (int j = 0; j < 65; j++) {
            float v = nfs[sub][k * 65 + j];
            a0 += v * Wgs[j * NC + c0];
            a1 += v * Wgs[j * NC + c0 + 1];
            a2 += v * Wgs[j * NC + c0 + 2];
            a3 += v * Wgs[j * NC + c0 + 3];
        }
        gs[sub][k * NC + c0] = tanhf(a0);
        gs[sub][k * NC + c0 + 1] = tanhf(a1);
        gs[sub][k * NC + c0 + 2] = tanhf(a2);
        gs[sub][k * NC + c0 + 3] = tanhf(a3);
    }
    __syncthreads();
    if (tid < NF) {
        xa[sub][tid] = xq[(size_t)b * NF + tid];
    } else if (tid < NF + NC) {
        int c = tid - NF;
        float s = 0.f;
#pragma unroll
        for (int k = 0; k < NK; k++) s += gs[sub][k * NC + c];
        xa[sub][tid] = s;
    }
    __syncthreads();

    float s = b1[tid];
#pragma unroll 8
    for (int i = 0; i < NF + NC; i++) s += xa[sub][i] * W1[i * NH + tid];
    float oh = tanhf(s);
    float r = oh * Wl[tid];
#pragma unroll
    for (int off = 16; off > 0; off >>= 1) r += __shfl_down_sync(0xffffffffu, r, off);
    if ((tid & 31) == 0) red[sub][tid >> 5] = r;
    __syncthreads();
    if (tid == 0) {
        float t = red[sub][0] + red[sub][1] + red[sub][2] + red[sub][3] + bl[0];
        out[b] = 1.f / (1.f + expf(-t));
    }
}

// ============================================================
extern "C" void kernel_launch(void* const* d_in, const int* in_sizes, int n_in,
                              void* d_out, int out_size) {
    (void)in_sizes; (void)n_in; (void)out_size;
    const float* xq = (const float*)d_in[0];
    const float* Xd = (const float*)d_in[1];
    const float* yv = (const float*)d_in[2];
    const float* Wg = (const float*)d_in[3];
    const float* bg = (const float*)d_in[4];
    const float* W1 = (const float*)d_in[5];
    const float* b1 = (const float*)d_in[6];
    const float* Wl = (const float*)d_in[7];
    const float* bl = (const float*)d_in[8];
    float* out = (float*)d_out;

    cudaFuncSetAttribute(mma_kernel<0, SAMPLE_TILES>, cudaFuncAttributeMaxDynamicSharedMemorySize, SM_TOTAL);
    cudaFuncSetAttribute(mma_kernel<1, MAIN_TILES>, cudaFuncAttributeMaxDynamicSharedMemorySize, SM_TOTAL);

    prep_kernel<<<NDPAD / 64, 256>>>(Xd, xq);
    mma_kernel<0, SAMPLE_TILES><<<dim3(NQ / MT, SAMPLE_SLICES), 256, SM_TOTAL>>>();
    tau_kernel<<<NQ, 256>>>();
    mma_kernel<1, MAIN_TILES><<<dim3(NQ / MT, NSL), 256, SM_TOTAL>>>();
    rsel_kernel<<<NQ, 256>>>(xq, Xd);
    mlp_kernel<<<NQ / 2, 256>>>(xq, Xd, yv, Wg, bg, W1, b1, Wl, bl, out);
}

// round 16
// speedup vs baseline: 1.3508x; 1.0023x over previous
#include <cuda_runtime.h>
#include <cuda_bf16.h>
#include <math.h>
#include <stdint.h>

// ---------------- problem constants ----------------
#define NQ 1024
#define ND 200000
#define NF 64
#define NK 32
#define NC 16
#define NH 128

#define MT 128           // queries per CTA
#define NT 128           // points per smem stage
#define NSL 54           // main-pass slices -> grid (8,54)=432 CTAs (one occ-3 wave)
#define MAIN_TILES 27    // 54*27*128 = 186624 >= 200000-16384
#define SN 16384         // sample size (main pass skips these points)
#define NDPAD 203008     // SN + 54*27*128
#define SAMPLE_SLICES 32
#define SAMPLE_TILES 4   // 32*4*128 = 16384
#define CAP 4096
#define MARGIN 4.0f      // mma approx + bf16-store safety margin
#define BIGV 3.0e38f

// ---------------- static device scratch ----------------
__device__ float          g_xxp[NDPAD];
__device__ __nv_bfloat16  g_Xb[(size_t)NDPAD * NF];
__device__ __nv_bfloat16  g_Qb[(size_t)NQ * NF];
__device__ unsigned short g_Du[(size_t)NQ * SN];   // radix-transformed bf16 keys
__device__ float          g_tau[NQ];
__device__ int            g_cnt[NQ];
__device__ int            g_si[(size_t)NQ * CAP];
__device__ int            g_topk[NQ * NK];

// ---------------- helpers ----------------
__device__ __forceinline__ uint32_t smem_u32(const void* p) {
    uint32_t a;
    asm("{ .reg .u64 t; cvta.to.shared.u64 t, %1; cvt.u32.u64 %0, t; }" : "=r"(a) : "l"(p));
    return a;
}
#define SWZ128(o) ((o) ^ (((o) >> 3) & 0x70))

__device__ __forceinline__ void cpa16(uint32_t d, const void* s) {
    asm volatile("cp.async.cg.shared.global [%0], [%1], 16;" :: "r"(d), "l"(s) : "memory");
}
#define CPA_COMMIT() asm volatile("cp.async.commit_group;" ::: "memory")
#define CPA_WAIT1()  asm volatile("cp.async.wait_group 1;" ::: "memory")

__device__ __forceinline__ void ldsm4(uint32_t* r, uint32_t a) {
    asm volatile("ldmatrix.sync.aligned.m8n8.x4.shared.b16 {%0,%1,%2,%3}, [%4];"
                 : "=r"(r[0]), "=r"(r[1]), "=r"(r[2]), "=r"(r[3]) : "r"(a));
}
__device__ __forceinline__ void mma16816(float* d, const uint32_t* a, const uint32_t* b) {
    asm volatile(
        "mma.sync.aligned.m16n8k16.row.col.f32.bf16.bf16.f32 "
        "{%0,%1,%2,%3}, {%4,%5,%6,%7}, {%8,%9}, {%0,%1,%2,%3};"
        : "+f"(d[0]), "+f"(d[1]), "+f"(d[2]), "+f"(d[3])
        : "r"(a[0]), "r"(a[1]), "r"(a[2]), "r"(a[3]), "r"(b[0]), "r"(b[1]));
}
__device__ __forceinline__ unsigned short f2bf(float v) {
    __nv_bfloat16 h = __float2bfloat16(v);
    return *(unsigned short*)&h;
}
// bf16 -> monotonic 16-bit radix key (done once, in the GEMM epilogue)
__device__ __forceinline__ unsigned short f2key(float v) {
    unsigned short h = f2bf(v);
    return (h & 0x8000u) ? (unsigned short)~h : (unsigned short)(h | 0x8000u);
}
// inverse: radix key -> float value
__device__ __forceinline__ float keyval(unsigned short k) {
    unsigned short bb = (k & 0x8000u) ? (unsigned short)(k ^ 0x8000u) : (unsigned short)~k;
    return __uint_as_float((unsigned)bb << 16);
}

// ---------------- smem layout of MMA kernel (bytes) ----------------
#define SMQ     0
#define SMX(s)  (16384 + (s) * 16384)
#define SMXX(s) (65536 + (s) * 512)
#define SMTAU   67072
#define SM_TOTAL 67584

// ============================================================
// prep: exact fp32 norms + bf16 X conversion + padding.
// Also (fused) converts Q to bf16(-2x) and zeroes g_cnt.
// ============================================================
__global__ void prep_kernel(const float* __restrict__ Xd, const float* __restrict__ xq) {
    const int gid = blockIdx.x * 256 + threadIdx.x;

    if (gid < NQ * NF / 2) {
        float2 v = ((const float2*)xq)[gid];
        __nv_bfloat162 h = __floats2bfloat162_rn(-2.f * v.x, -2.f * v.y);
        ((__nv_bfloat162*)g_Qb)[gid] = h;
    }
    if (gid < NQ) g_cnt[gid] = 0;

    int r = blockIdx.x * 64 + (threadIdx.x >> 2);
    int part = threadIdx.x & 3;
    if (r >= NDPAD) return;
    uint4* dst = (uint4*)(g_Xb + (size_t)r * NF) + part * 2;
    if (r < ND) {
        const float4* row = (const float4*)(Xd + (size_t)r * NF) + part * 4;
        float4 v[4];
        float s = 0.f;
#pragma unroll
        for (int l = 0; l < 4; l++) {
            v[l] = row[l];
            s += v[l].x * v[l].x + v[l].y * v[l].y + v[l].z * v[l].z + v[l].w * v[l].w;
        }
        s += __shfl_xor_sync(0xffffffffu, s, 1);
        s += __shfl_xor_sync(0xffffffffu, s, 2);
        if (part == 0) g_xxp[r] = s;
        unsigned u[8];
#pragma unroll
        for (int l = 0; l < 4; l++) {
            __nv_bfloat162 h0 = __floats2bfloat162_rn(v[l].x, v[l].y);
            __nv_bfloat162 h1 = __floats2bfloat162_rn(v[l].z, v[l].w);
            u[l * 2]     = *(unsigned*)&h0;
            u[l * 2 + 1] = *(unsigned*)&h1;
        }
        dst[0] = make_uint4(u[0], u[1], u[2], u[3]);
        dst[1] = make_uint4(u[4], u[5], u[6], u[7]);
    } else {
        if (part == 0) g_xxp[r] = BIGV;
        uint4 z = make_uint4(0, 0, 0, 0);
        dst[0] = z; dst[1] = z;
    }
}

// ============================================================
// MMA kernel: warp tile 32q x 32n (4x2 warp grid), CTA 128q x 128n/stage,
// 3-stage cp.async ring, one __syncthreads per stage, occ 3.
// A (Q) fragments hoisted for the whole slice (32 regs).
// MODE 0: write radix keys of sample-region scores to g_Du
// MODE 1: filter vs g_tau over points [SN, NDPAD)
// ============================================================
template <int MODE, int NTILES>
__global__ void __launch_bounds__(256, 3)
mma_kernel() {
    extern __shared__ char smem[];
    const uint32_t sb = smem_u32(smem);
    const int tid = threadIdx.x;
    const int lane = tid & 31;
    const int wid = tid >> 5;
    const int mtile = blockIdx.x;
    const int base = (MODE == 1 ? SN : 0) + blockIdx.y * NTILES * NT;

    // load Q tile into swizzled smem (128 rows x 128B)
    {
        const uint4* qsrc = (const uint4*)(g_Qb + (size_t)mtile * MT * NF);
#pragma unroll
        for (int c = 0; c < 4; c++) {
            int ch = tid + c * 256;
            int row = ch >> 3, col = ch & 7;
            *(uint4*)(smem + SMQ + SWZ128(row * 128 + col * 16)) = qsrc[ch];
        }
    }
    if (MODE == 1 && tid < MT) ((float*)(smem + SMTAU))[tid] = g_tau[mtile * MT + tid];

    // prologue: issue stages 0 and 1
#pragma unroll
    for (int s = 0; s < 2; s++) {
        if (s < NTILES) {
            const uint4* xs = (const uint4*)(g_Xb + (size_t)(base + s * NT) * NF);
#pragma unroll
            for (int c = 0; c < 4; c++) {
                int ch = tid + c * 256;
                int row = ch >> 3, col = ch & 7;
                cpa16(sb + SMX(s) + SWZ128(row * 128 + col * 16), xs + ch);
            }
            if (tid < 32) cpa16(sb + SMXX(s) + tid * 16, g_xxp + base + s * NT + tid * 4);
        }
        CPA_COMMIT();
    }
    __syncthreads();   // Q (and tau) visible

    const int wr = wid >> 1;
    const int wc = wid & 1;
    const int m0 = wr * 32;
    const int nb = wc * 32;
    const int tq = lane >> 2;
    const int tn2 = (lane & 3) * 2;

    const int a_row = lane & 15, a_kh = lane >> 4;
    const int b_row = (lane & 7) | ((lane >> 4) << 3), b_kh = (lane >> 3) & 1;

    uint32_t afr[4][8];
#pragma unroll
    for (int ks = 0; ks < 4; ks++)
#pragma unroll
        for (int mf = 0; mf < 2; mf++) {
            uint32_t addr = sb + SMQ +
                SWZ128((m0 + mf * 16 + a_row) * 128 + ks * 32 + a_kh * 16);
            ldsm4(&afr[ks][mf * 4], addr);
        }

    float tr[4], tmax = -BIGV;
    if (MODE == 1) {
        const float* tsm = (const float*)(smem + SMTAU);
#pragma unroll
        for (int mf = 0; mf < 2; mf++)
#pragma unroll
            for (int h = 0; h < 2; h++) {
                tr[mf * 2 + h] = tsm[m0 + mf * 16 + h * 8 + tq];
                tmax = fmaxf(tmax, tr[mf * 2 + h]);
            }
    }

    for (int t = 0; t < NTILES; t++) {
        const int t0 = base + t * NT;
        const int st = t % 3;
        const uint32_t xb  = SMX(st);
        const uint32_t xxb = SMXX(st);

        CPA_WAIT1();
        __syncthreads();

        if (t + 2 < NTILES) {
            const int ps = (t + 2) % 3;
            const uint4* xs = (const uint4*)(g_Xb + (size_t)(t0 + 2 * NT) * NF);
#pragma unroll
            for (int c = 0; c < 4; c++) {
                int ch = tid + c * 256;
                int row = ch >> 3, col = ch & 7;
                cpa16(sb + SMX(ps) + SWZ128(row * 128 + col * 16), xs + ch);
            }
            if (tid < 32) cpa16(sb + SMXX(ps) + tid * 16, g_xxp + t0 + 2 * NT + tid * 4);
        }
        CPA_COMMIT();

#pragma unroll
        for (int half = 0; half < 2; half++) {
            const int nh = half * 64 + nb;

            float d[2][4][4];
#pragma unroll
            for (int i = 0; i < 2; i++)
#pragma unroll
                for (int j = 0; j < 4; j++)
#pragma unroll
                    for (int k = 0; k < 4; k++) d[i][j][k] = 0.f;

#pragma unroll
            for (int ks = 0; ks < 4; ks++) {
                uint32_t b[4][2];
#pragma unroll
                for (int h = 0; h < 2; h++) {
                    uint32_t r[4];
                    uint32_t addr = sb + xb +
                        SWZ128((nh + h * 16 + b_row) * 128 + ks * 32 + b_kh * 16);
                    ldsm4(r, addr);
                    b[h * 2][0] = r[0]; b[h * 2][1] = r[1];
                    b[h * 2 + 1][0] = r[2]; b[h * 2 + 1][1] = r[3];
                }
#pragma unroll
                for (int mf = 0; mf < 2; mf++)
#pragma unroll
                    for (int nf = 0; nf < 4; nf++)
                        mma16816(d[mf][nf], &afr[ks][mf * 4], b[nf]);
            }

            const float* xxs = (const float*)(smem + xxb);
            float2 xv[4];
#pragma unroll
            for (int nf = 0; nf < 4; nf++) xv[nf] = *(const float2*)(xxs + nh + nf * 8 + tn2);

            float vmin = BIGV;
#pragma unroll
            for (int mf = 0; mf < 2; mf++)
#pragma unroll
                for (int nf = 0; nf < 4; nf++) {
                    d[mf][nf][0] += xv[nf].x;
                    d[mf][nf][1] += xv[nf].y;
                    d[mf][nf][2] += xv[nf].x;
                    d[mf][nf][3] += xv[nf].y;
                    if (MODE == 1)
                        vmin = fminf(vmin, fminf(fminf(d[mf][nf][0], d[mf][nf][1]),
                                                 fminf(d[mf][nf][2], d[mf][nf][3])));
                }

            if (MODE == 0) {
#pragma unroll
                for (int mf = 0; mf < 2; mf++)
#pragma unroll
                    for (int h = 0; h < 2; h++) {
                        const int gq = mtile * MT + m0 + mf * 16 + h * 8 + tq;
                        unsigned short* dst = g_Du + (size_t)gq * SN + (t0 + nh + tn2);
#pragma unroll
                        for (int nf = 0; nf < 4; nf++) {
                            unsigned short u0 = f2key(d[mf][nf][h * 2]);
                            unsigned short u1 = f2key(d[mf][nf][h * 2 + 1]);
                            *(unsigned*)(dst + nf * 8) = (unsigned)u0 | ((unsigned)u1 << 16);
                        }
                    }
            } else if (vmin <= tmax) {
#pragma unroll
                for (int mf = 0; mf < 2; mf++)
#pragma unroll
                    for (int h = 0; h < 2; h++) {
                        const int gq = mtile * MT + m0 + mf * 16 + h * 8 + tq;
                        const float tau = tr[mf * 2 + h];
#pragma unroll
                        for (int nf = 0; nf < 4; nf++) {
                            float v0 = d[mf][nf][h * 2];
                            float v1 = d[mf][nf][h * 2 + 1];
                            if (v0 <= tau) {
                                int pos = atomicAdd(&g_cnt[gq], 1);
                                if (pos < CAP) g_si[(size_t)gq * CAP + pos] = t0 + nh + nf * 8 + tn2;
                            }
                            if (v1 <= tau) {
                                int pos = atomicAdd(&g_cnt[gq], 1);
                                if (pos < CAP) g_si[(size_t)gq * CAP + pos] = t0 + nh + nf * 8 + tn2 + 1;
                            }
                        }
                    }
            }
        }
    }
}

// ============================================================
// tau: radix-select 32nd smallest key + margin, THEN filter the
// sample region from the register-cached keys (appends survivors),
// so the main pass can skip points [0, SN).
// ============================================================
__global__ void tau_kernel() {
    __shared__ unsigned hist[8][256];        // 8KB
    __shared__ unsigned s_prefix;
    __shared__ int s_rank;
    __shared__ float s_tauf;
    const int b = blockIdx.x, tid = threadIdx.x;
    const int w = tid >> 5;
    const uint4* src = (const uint4*)(g_Du + (size_t)b * SN);

    unsigned kreg[32];                        // 64 keys cached in registers

    // ---- pass 1: load + high-byte histogram ----
#pragma unroll
    for (int j = 0; j < 8; j++) hist[j][tid] = 0;
    __syncthreads();
#pragma unroll
    for (int c = 0; c < 8; c++) {
        uint4 v = src[tid + c * 256];
        kreg[c * 4 + 0] = v.x; kreg[c * 4 + 1] = v.y;
        kreg[c * 4 + 2] = v.z; kreg[c * 4 + 3] = v.w;
#pragma unroll
        for (int e = 0; e < 4; e++) {
            unsigned k = kreg[c * 4 + e];
            atomicAdd(&hist[w][(k >> 8) & 255u], 1u);
            atomicAdd(&hist[w][(k >> 24) & 255u], 1u);
        }
    }
    __syncthreads();
    {
        unsigned tot = hist[0][tid];
#pragma unroll
        for (int j = 1; j < 8; j++) tot += hist[j][tid];
        hist[0][tid] = tot;
    }
    __syncthreads();
    if (tid == 0) {
        int r = NK;
        unsigned cum = 0;
        for (int k = 0; k < 256; k++) {
            unsigned h = hist[0][k];
            if (cum + h >= (unsigned)r) { s_rank = r - (int)cum; s_prefix = (unsigned)k << 8; break; }
            cum += h;
        }
    }
    __syncthreads();
    const unsigned pfx = s_prefix;

    // ---- pass 2: low byte among matching keys, from registers ----
#pragma unroll
    for (int j = 0; j < 8; j++) hist[j][tid] = 0;
    __syncthreads();
#pragma unroll
    for (int i = 0; i < 32; i++) {
        unsigned k = kreg[i];
        unsigned lo = k & 0xFFFFu, hi = k >> 16;
        if ((lo & 0xFF00u) == pfx) atomicAdd(&hist[w][lo & 255u], 1u);
        if ((hi & 0xFF00u) == pfx) atomicAdd(&hist[w][hi & 255u], 1u);
    }
    __syncthreads();
    {
        unsigned tot = hist[0][tid];
#pragma unroll
        for (int j = 1; j < 8; j++) tot += hist[j][tid];
        hist[0][tid] = tot;
    }
    __syncthreads();
    if (tid == 0) {
        int r = s_rank;
        unsigned cum = 0;
        unsigned key = pfx;
        for (int k = 0; k < 256; k++) {
            unsigned h = hist[0][k];
            if (cum + h >= (unsigned)r) { key = pfx | (unsigned)k; break; }
            cum += h;
        }
        float tf = keyval((unsigned short)key) + MARGIN;
        g_tau[b] = tf;
        s_tauf = tf;
    }
    __syncthreads();
    const float tauf = s_tauf;

    // ---- filter the sample region from the register cache ----
#pragma unroll
    for (int c = 0; c < 8; c++) {
#pragma unroll
        for (int e = 0; e < 4; e++) {
            unsigned k = kreg[c * 4 + e];
            int jbase = (tid + c * 256) * 8 + e * 2;
            float v0 = keyval((unsigned short)(k & 0xFFFFu));
            float v1 = keyval((unsigned short)(k >> 16));
            if (v0 <= tauf) {
                int pos = atomicAdd(&g_cnt[b], 1);
                if (pos < CAP) g_si[(size_t)b * CAP + pos] = jbase;
            }
            if (v1 <= tauf) {
                int pos = atomicAdd(&g_cnt[b], 1);
                if (pos < CAP) g_si[(size_t)b * CAP + pos] = jbase + 1;
            }
        }
    }
}

// ============================================================
// rescore + select fused: exact fp32 scores into smem, then
// exact top-32 with (val, idx) tie-break. One block per query.
// ============================================================
__global__ void rsel_kernel(const float* __restrict__ xq, const float* __restrict__ Xd) {
    __shared__ float sv[CAP];
    __shared__ int si[CAP];
    __shared__ float xs[NF];
    __shared__ float rv[8];
    __shared__ int ri[8], rp[8];
    const int b = blockIdx.x, tid = threadIdx.x;
    const int w = tid >> 5, lane = tid & 31;

    if (tid < NF) xs[tid] = xq[(size_t)b * NF + tid];
    int c = g_cnt[b]; if (c > CAP) c = CAP;
    const int cpad = (c + 255) & ~255;
    for (int i = tid; i < cpad; i += 256) { sv[i] = BIGV; si[i] = 0x7FFFFFFF; }
    __syncthreads();

    float2 xv = *(const float2*)(xs + 2 * lane);
    for (int s = w; s < c; s += 8) {
        int n = g_si[(size_t)b * CAP + s];
        float2 Xv = *(const float2*)(Xd + (size_t)n * NF + 2 * lane);
        float p = xv.x * Xv.x + xv.y * Xv.y;
#pragma unroll
        for (int off = 16; off > 0; off >>= 1) p += __shfl_xor_sync(0xffffffffu, p, off);
        if (lane == 0) { sv[s] = g_xxp[n] - 2.f * p; si[s] = n; }
    }
    __syncthreads();

    for (int r = 0; r < NK; r++) {
        float bv = BIGV; int bi = 0x7FFFFFFF; int bp = 0;
        for (int i = tid; i < cpad; i += 256) {
            float v = sv[i]; int ix = si[i];
            if (v < bv || (v == bv && ix < bi)) { bv = v; bi = ix; bp = i; }
        }
#pragma unroll
        for (int off = 16; off > 0; off >>= 1) {
            float ov = __shfl_down_sync(0xffffffffu, bv, off);
            int oi = __shfl_down_sync(0xffffffffu, bi, off);
            int op = __shfl_down_sync(0xffffffffu, bp, off);
            if (ov < bv || (ov == bv && oi < bi)) { bv = ov; bi = oi; bp = op; }
        }
        if (lane == 0) { rv[w] = bv; ri[w] = bi; rp[w] = bp; }
        __syncthreads();
        if (tid == 0) {
            for (int wi = 1; wi < 8; wi++)
                if (rv[wi] < rv[0] || (rv[wi] == rv[0] && ri[wi] < ri[0])) {
                    rv[0] = rv[wi]; ri[0] = ri[wi]; rp[0] = rp[wi];
                }
            g_topk[b * NK + r] = ri[0];
            sv[rp[0]] = BIGV; si[rp[0]] = 0x7FFFFFFF;
        }
        __syncthreads();
    }
}

// ============================================================
// mlp: gather neighbors + gated MLP head.
// 2 queries per 256-thread block (sub-blocks of 128).
// ============================================================
__global__ void mlp_kernel(const float* __restrict__ xq, const float* __restrict__ Xd,
                           const float* __restrict__ yv, const float* __restrict__ Wg,
                           const float* __restrict__ bg, const float* __restrict__ W1,
                           const float* __restrict__ b1, const float* __restrict__ Wl,
                           const float* __restrict__ bl, float* __restrict__ out) {
    __shared__ float nfs[2][NK * 65];
    __shared__ float Wgs[65 * NC];
    __shared__ float gs[2][NK * NC];
    __shared__ float xa[2][NF + NC];
    __shared__ float red[2][4];
    __shared__ int idx[2][NK];
    const int sub = threadIdx.x >> 7;
    const int tid = threadIdx.x & 127;
    const int b = blockIdx.x * 2 + sub;

    if (tid < NK) idx[sub][tid] = g_topk[b * NK + tid];
    for (int i = threadIdx.x; i < 65 * NC; i += 256) Wgs[i] = Wg[i];
    __syncthreads();
    for (int i = tid; i < NK * NF; i += 128) {
        int k = i >> 6, f = i & 63;
        nfs[sub][k * 65 + f] = Xd[(size_t)idx[sub][k] * NF + f];
    }
    if (tid < NK) nfs[sub][tid * 65 + 64] = yv[idx[sub][tid]];
    __syncthreads();

    {
        int k = tid & 31, c0 = (tid >> 5) * 4;
        float a0 = bg[c0], a1 = bg[c0 + 1], a2 = bg[c0 + 2], a3 = bg[c0 + 3];
#pragma unroll 5
        for (int j = 0; j < 65; j++) {
            float v = nfs[sub][k * 65 + j];
            a0 += v * Wgs[j * NC + c0];
            a1 += v * Wgs[j * NC + c0 + 1];
            a2 += v * Wgs[j * NC + c0 + 2];
            a3 += v * Wgs[j * NC + c0 + 3];
        }
        gs[sub][k * NC + c0] = tanhf(a0);
        gs[sub][k * NC + c0 + 1] = tanhf(a1);
        gs[sub][k * NC + c0 + 2] = tanhf(a2);
        gs[sub][k * NC + c0 + 3] = tanhf(a3);
    }
    __syncthreads();
    if (tid < NF) {
        xa[sub][tid] = xq[(size_t)b * NF + tid];
    } else if (tid < NF + NC) {
        int c = tid - NF;
        float s = 0.f;
#pragma unroll
        for (int k = 0; k < NK; k++) s += gs[sub][k * NC + c];
        xa[sub][tid] = s;
    }
    __syncthreads();

    float s = b1[tid];
#pragma unroll 8
    for (int i = 0; i < NF + NC; i++) s += xa[sub][i] * W1[i * NH + tid];
    float oh = tanhf(s);
    float r = oh * Wl[tid];
#pragma unroll
    for (int off = 16; off > 0; off >>= 1) r += __shfl_down_sync(0xffffffffu, r, off);
    if ((tid & 31) == 0) red[sub][tid >> 5] = r;
    __syncthreads();
    if (tid == 0) {
        float t = red[sub][0] + red[sub][1] + red[sub][2] + red[sub][3] + bl[0];
        out[b] = 1.f / (1.f + expf(-t));
    }
}

// ============================================================
extern "C" void kernel_launch(void* const* d_in, const int* in_sizes, int n_in,
                              void* d_out, int out_size) {
    (void)in_sizes; (void)n_in; (void)out_size;
    const float* xq = (const float*)d_in[0];
    const float* Xd = (const float*)d_in[1];
    const float* yv = (const float*)d_in[2];
    const float* Wg = (const float*)d_in[3];
    const float* bg = (const float*)d_in[4];
    const float* W1 = (const float*)d_in[5];
    const float* b1 = (const float*)d_in[6];
    const float* Wl = (const float*)d_in[7];
    const float* bl = (const float*)d_in[8];
    float* out = (float*)d_out;

    cudaFuncSetAttribute(mma_kernel<0, SAMPLE_TILES>, cudaFuncAttributeMaxDynamicSharedMemorySize, SM_TOTAL);
    cudaFuncSetAttribute(mma_kernel<1, MAIN_TILES>, cudaFuncAttributeMaxDynamicSharedMemorySize, SM_TOTAL);

    prep_kernel<<<NDPAD / 64, 256>>>(Xd, xq);
    mma_kernel<0, SAMPLE_TILES><<<dim3(NQ / MT, SAMPLE_SLICES), 256, SM_TOTAL>>>();
    tau_kernel<<<NQ, 256>>>();
    mma_kernel<1, MAIN_TILES><<<dim3(NQ / MT, NSL), 256, SM_TOTAL>>>();
    rsel_kernel<<<NQ, 256>>>(xq, Xd);
    mlp_kernel<<<NQ / 2, 256>>>(xq, Xd, yv, Wg, bg, W1, b1, Wl, bl, out);
}